// round 2
// baseline (speedup 1.0000x reference)
#include <cuda_runtime.h>
#include <cstdint>
#include <math.h>

#define D 128
#define NMAX 100352
#define EMAX 131072
#define NQMAX 128
#define EQCAP 1024

// ---------------- static scratch (allocation-free rule) ----------------
__device__ float    g_Wnode[512 * D];           // [512,128] rows: W_left[:, :128] ; W_right[:, :128]
__device__ float    g_Wrel [512 * D];           // [512,128] rows: W_left[:,128:256] ; W_right[:,128:256]
__device__ float    g_Ql[NQMAX * 256];          // per-query left bias term
__device__ float    g_Qr[NQMAX * 256];          // per-query right bias term
__device__ float    g_Pnode[NMAX * 512];        // node_rep @ [Wl_h;Wr_h]^T
__device__ float    g_Prel [EMAX * 512];        // rel_emb  @ [Wl_r;Wr_r]^T
__device__ float    g_L  [EMAX * 256];          // leaky(left)
__device__ float    g_R1 [EMAX * 256];          // leaky(right)
__device__ float    g_R  [EMAX * 256];          // r1 @ Wc^T
__device__ float    g_logits[EMAX];
__device__ float    g_ex[EMAX];
__device__ float    g_attn[EMAX];
__device__ float    g_scoreE[EMAX];
__device__ unsigned g_ukey[EMAX];
__device__ unsigned g_segmax[NMAX];
__device__ float    g_denom[NMAX];
__device__ float    g_newrep[NMAX * D];
__device__ unsigned g_hist[NQMAX * 256];
__device__ unsigned g_prefix[NQMAX];
__device__ int      g_krem[NQMAX];
__device__ int      g_keepall[NQMAX];
__device__ int      g_eqcnt[NQMAX];
__device__ int      g_eqlist[NQMAX * EQCAP];
__device__ int      g_eqkeep[EMAX];

__device__ __forceinline__ float leaky(float x) { return x > 0.f ? x : 0.01f * x; }
__device__ __forceinline__ unsigned f2mono(float f) {
    unsigned b = __float_as_uint(f);
    return (b & 0x80000000u) ? ~b : (b | 0x80000000u);
}
__device__ __forceinline__ float mono2f(unsigned u) {
    return (u & 0x80000000u) ? __uint_as_float(u & 0x7fffffffu) : __uint_as_float(~u);
}

// ---------------- generic zero kernels ----------------
__global__ void kzero_f(float* p, int n) {
    int i = blockIdx.x * blockDim.x + threadIdx.x;
    if (i < n) p[i] = 0.f;
}
__global__ void k_zero_state(int NN, int E, int NQ) {
    int t = blockIdx.x * blockDim.x + threadIdx.x;
    if (t < NN) { g_segmax[t] = 0u; g_denom[t] = 0.f; }
    if (t < E)  g_eqkeep[t] = 0;
    if (t < NQ * 256) g_hist[t] = 0u;
}

// ---------------- weight repack ----------------
__global__ void k_repack(const float* __restrict__ Wl, const float* __restrict__ Wr) {
    int t = blockIdx.x * blockDim.x + threadIdx.x;
    if (t >= 512 * D) return;
    int j = t >> 7, k = t & 127;
    const float* src = (j < 256) ? (Wl + (size_t)j * 512) : (Wr + (size_t)(j - 256) * 512);
    g_Wnode[t] = src[k];
    g_Wrel[t]  = src[128 + k];
}

// ---------------- per-query precombine:  Ql = qs@Wl[:,256:384]^T + qr@Wl[:,384:512]^T + b ----------------
__global__ void k_qcomb(const float* __restrict__ qs, const float* __restrict__ qr,
                        const float* __restrict__ Wl, const float* __restrict__ bl,
                        const float* __restrict__ Wr, const float* __restrict__ br, int NQ) {
    int t = blockIdx.x * blockDim.x + threadIdx.x;
    if (t >= NQ * 256) return;
    int q = t >> 8, j = t & 255;
    const float* s  = qs + (size_t)q * D;
    const float* r  = qr + (size_t)q * D;
    const float* wl = Wl + (size_t)j * 512;
    const float* wr = Wr + (size_t)j * 512;
    float accl = bl[j], accr = br[j];
#pragma unroll 4
    for (int k = 0; k < D; k++) {
        float sv = s[k], rv = r[k];
        accl = fmaf(sv, wl[256 + k], accl);
        accl = fmaf(rv, wl[384 + k], accl);
        accr = fmaf(sv, wr[256 + k], accr);
        accr = fmaf(rv, wr[384 + k], accr);
    }
    g_Ql[t] = accl;
    g_Qr[t] = accr;
}

// ---------------- fp32 NT GEMM: C[M,N] = A[M,K] @ B[N,K]^T (+bias, leaky) ----------------
// 128x128 block, BK=8, 256 threads, 8x8 per-thread microtile
template <bool BIAS_LEAKY>
__global__ __launch_bounds__(256, 2) void gemm_nt(const float* __restrict__ A,
                                                  const float* __restrict__ B,
                                                  float* __restrict__ C,
                                                  const float* __restrict__ bias,
                                                  int M, int N, int K) {
    __shared__ float As[8][132];
    __shared__ float Bs[8][132];
    int bm = blockIdx.y * 128, bn = blockIdx.x * 128;
    int tid = threadIdx.x;
    int lr = tid >> 1;             // load row 0..127
    int lc = (tid & 1) * 4;        // k offset 0 or 4
    int tm = (tid >> 4) * 8;       // compute row base
    int tn = (tid & 15) * 8;       // compute col base
    float acc[8][8];
#pragma unroll
    for (int i = 0; i < 8; i++)
#pragma unroll
        for (int j = 0; j < 8; j++) acc[i][j] = 0.f;

    bool aok = (bm + lr) < M;
    bool bok = (bn + lr) < N;
    const float* Ap = A + (size_t)(bm + lr) * K + lc;
    const float* Bp = B + (size_t)(bn + lr) * K + lc;

    for (int k0 = 0; k0 < K; k0 += 8) {
        float4 a4 = aok ? *(const float4*)(Ap + k0) : make_float4(0.f, 0.f, 0.f, 0.f);
        float4 b4 = bok ? *(const float4*)(Bp + k0) : make_float4(0.f, 0.f, 0.f, 0.f);
        As[lc + 0][lr] = a4.x; As[lc + 1][lr] = a4.y; As[lc + 2][lr] = a4.z; As[lc + 3][lr] = a4.w;
        Bs[lc + 0][lr] = b4.x; Bs[lc + 1][lr] = b4.y; Bs[lc + 2][lr] = b4.z; Bs[lc + 3][lr] = b4.w;
        __syncthreads();
#pragma unroll
        for (int k = 0; k < 8; k++) {
            float a[8], b[8];
            *(float4*)(a)     = *(const float4*)&As[k][tm];
            *(float4*)(a + 4) = *(const float4*)&As[k][tm + 4];
            *(float4*)(b)     = *(const float4*)&Bs[k][tn];
            *(float4*)(b + 4) = *(const float4*)&Bs[k][tn + 4];
#pragma unroll
            for (int i = 0; i < 8; i++)
#pragma unroll
                for (int j = 0; j < 8; j++) acc[i][j] = fmaf(a[i], b[j], acc[i][j]);
        }
        __syncthreads();
    }
    // epilogue
#pragma unroll
    for (int i = 0; i < 8; i++) {
        int m = bm + tm + i;
        if (m >= M) break;
        float* Cr = C + (size_t)m * N + bn + tn;
#pragma unroll
        for (int j = 0; j < 8; j += 4) {
            float4 v;
            v.x = acc[i][j + 0]; v.y = acc[i][j + 1]; v.z = acc[i][j + 2]; v.w = acc[i][j + 3];
            if (BIAS_LEAKY) {
                v.x = leaky(v.x + bias[bn + tn + j + 0]);
                v.y = leaky(v.y + bias[bn + tn + j + 1]);
                v.z = leaky(v.z + bias[bn + tn + j + 2]);
                v.w = leaky(v.w + bias[bn + tn + j + 3]);
            }
            *(float4*)(Cr + j) = v;
        }
    }
}

// ---------------- edge assembly: L = leaky(Pnode[i,:256]+Prel[e,:256]+Ql[q]), R1 similarly ----------------
__global__ void k_assemble(const int* __restrict__ idx_i, const int* __restrict__ idx_j,
                           const int* __restrict__ qidx, int E) {
    int t = blockIdx.x * blockDim.x + threadIdx.x;
    int e = t >> 6;
    if (e >= E) return;
    int c = (t & 63) * 4;
    int i = idx_i[e], j = idx_j[e], q = qidx[e];

    float4 pl = *(const float4*)(g_Pnode + (size_t)i * 512 + c);
    float4 rl = *(const float4*)(g_Prel + (size_t)e * 512 + c);
    float4 ql = *(const float4*)(g_Ql + (size_t)q * 256 + c);
    float4 o;
    o.x = leaky(pl.x + rl.x + ql.x);
    o.y = leaky(pl.y + rl.y + ql.y);
    o.z = leaky(pl.z + rl.z + ql.z);
    o.w = leaky(pl.w + rl.w + ql.w);
    *(float4*)(g_L + (size_t)e * 256 + c) = o;

    float4 pr = *(const float4*)(g_Pnode + (size_t)j * 512 + 256 + c);
    float4 rr = *(const float4*)(g_Prel + (size_t)e * 512 + 256 + c);
    float4 qq = *(const float4*)(g_Qr + (size_t)q * 256 + c);
    float4 o2;
    o2.x = leaky(pr.x + rr.x + qq.x);
    o2.y = leaky(pr.y + rr.y + qq.y);
    o2.z = leaky(pr.z + rr.z + qq.z);
    o2.w = leaky(pr.w + rr.w + qq.w);
    *(float4*)(g_R1 + (size_t)e * 256 + c) = o2;
}

// ---------------- logits = sum_n L[e,n]*(R[e,n]+bc[n]) ; seg_max atomic ----------------
__global__ void k_logits(const float* __restrict__ bc, const int* __restrict__ idx_i, int E) {
    int gw = (blockIdx.x * blockDim.x + threadIdx.x) >> 5;
    int lane = threadIdx.x & 31;
    if (gw >= E) return;
    const float* Lr = g_L + (size_t)gw * 256;
    const float* Rr = g_R + (size_t)gw * 256;
    float s = 0.f;
    int c = lane * 4;
#pragma unroll
    for (int h = 0; h < 2; h++, c += 128) {
        float4 l = *(const float4*)(Lr + c);
        float4 r = *(const float4*)(Rr + c);
        float4 b = *(const float4*)(bc + c);
        s = fmaf(l.x, r.x + b.x, s);
        s = fmaf(l.y, r.y + b.y, s);
        s = fmaf(l.z, r.z + b.z, s);
        s = fmaf(l.w, r.w + b.w, s);
    }
#pragma unroll
    for (int o = 16; o; o >>= 1) s += __shfl_xor_sync(0xffffffffu, s, o);
    if (lane == 0) {
        g_logits[gw] = s;
        atomicMax(&g_segmax[idx_i[gw]], f2mono(s));
    }
}

// ---------------- exp + denom ----------------
__global__ void k_ex(const int* __restrict__ idx_i, int E) {
    int e = blockIdx.x * blockDim.x + threadIdx.x;
    if (e >= E) return;
    int i = idx_i[e];
    float m = mono2f(g_segmax[i]);
    float ex = expf(g_logits[e] - m);
    g_ex[e] = ex;
    atomicAdd(&g_denom[i], ex);
}

// ---------------- attn / target_score / radix keys ----------------
__global__ void k_score(const int* __restrict__ idx_i, const float* __restrict__ visited, int E) {
    int e = blockIdx.x * blockDim.x + threadIdx.x;
    if (e >= E) return;
    int i = idx_i[e];
    float a = g_ex[e] / g_denom[i];
    g_attn[e] = a;
    float sc = a * visited[i];
    g_scoreE[e] = sc;
    g_ukey[e] = __float_as_uint(sc);   // sc >= 0 -> bits monotonic
}

// ---------------- top-k radix select (4x 8-bit passes, descending) ----------------
__global__ void k_init_select(const int* __restrict__ max_edges, int NQ) {
    int q = blockIdx.x * blockDim.x + threadIdx.x;
    if (q < NQ) {
        g_krem[q] = max_edges ? *max_edges : 1024;
        g_prefix[q] = 0u;
        g_keepall[q] = 0;
        g_eqcnt[q] = 0;
    }
}
__global__ void k_hist(const int* __restrict__ qidx, int E, int shift) {
    int e = blockIdx.x * blockDim.x + threadIdx.x;
    if (e >= E) return;
    int q = qidx[e];
    if (g_keepall[q]) return;
    unsigned u = g_ukey[e];
    if (shift < 24 && ((u >> (shift + 8)) != (g_prefix[q] >> (shift + 8)))) return;
    atomicAdd(&g_hist[(q << 8) + ((u >> shift) & 255u)], 1u);
}
__global__ void k_scan(int shift, int NQ) {
    int q = threadIdx.x;
    if (q < NQ && !g_keepall[q]) {
        unsigned kr = (unsigned)g_krem[q];
        unsigned c = 0;
        int found = 0;
        for (int b = 255; b >= 0; b--) {
            unsigned h = g_hist[(q << 8) + b];
            if (c + h >= kr) {
                g_prefix[q] |= ((unsigned)b) << shift;
                g_krem[q] = (int)(kr - c);
                found = 1;
                break;
            }
            c += h;
        }
        if (!found) g_keepall[q] = 1;   // whole group fits under k
    }
    __syncthreads();
    for (int t = threadIdx.x; t < NQ * 256; t += blockDim.x) g_hist[t] = 0u;
}
__global__ void k_eq_gather(const int* __restrict__ qidx, int E) {
    int e = blockIdx.x * blockDim.x + threadIdx.x;
    if (e >= E) return;
    int q = qidx[e];
    if (g_keepall[q]) return;
    if (g_ukey[e] == g_prefix[q]) {
        int p = atomicAdd(&g_eqcnt[q], 1);
        if (p < EQCAP) g_eqlist[q * EQCAP + p] = e;
    }
}
__global__ void k_eq_resolve(int NQ) {
    int q = blockIdx.x;
    if (q >= NQ || g_keepall[q]) return;
    int n = min(g_eqcnt[q], EQCAP);
    int keq = g_krem[q];
    for (int t = threadIdx.x; t < n; t += blockDim.x) {
        int me = g_eqlist[q * EQCAP + t];
        if (n <= keq) { g_eqkeep[me] = 1; continue; }
        int cnt = 0;
        for (int jj = 0; jj < n; jj++) cnt += (g_eqlist[q * EQCAP + jj] < me);
        if (cnt < keq) g_eqkeep[me] = 1;   // stable-sort tiebreak: smallest original index wins
    }
}

// ---------------- pruned aggregation (scatter atomics) ----------------
__global__ void k_aggregate(const float* __restrict__ node_rep, const int* __restrict__ qidx,
                            const int* __restrict__ idx_i, const int* __restrict__ idx_j,
                            float* __restrict__ out_score, int E) {
    int w = (blockIdx.x * blockDim.x + threadIdx.x) >> 5;
    int lane = threadIdx.x & 31;
    if (w >= E) return;
    int q = qidx[w];
    bool keep = g_keepall[q] || (g_ukey[w] > g_prefix[q]) || g_eqkeep[w];
    if (!keep) return;
    int i = idx_i[w], j = idx_j[w];
    if (lane == 0) atomicAdd(out_score + j, g_scoreE[w]);
    float a = g_attn[w];
    float4 h = *(const float4*)(node_rep + (size_t)i * D + lane * 4);
#if __CUDA_ARCH__ >= 900
    atomicAdd((float4*)(g_newrep + (size_t)j * D + lane * 4),
              make_float4(a * h.x, a * h.y, a * h.z, a * h.w));
#else
    float* dst = g_newrep + (size_t)j * D + lane * 4;
    atomicAdd(dst + 0, a * h.x);
    atomicAdd(dst + 1, a * h.y);
    atomicAdd(dst + 2, a * h.z);
    atomicAdd(dst + 3, a * h.w);
#endif
}

// ---------------- launch ----------------
extern "C" void kernel_launch(void* const* d_in, const int* in_sizes, int n_in,
                              void* d_out, int out_size) {
    const float* visited  = (const float*)d_in[0];
    const float* node_rep = (const float*)d_in[1];
    const float* qsrc     = (const float*)d_in[2];
    const float* qrel     = (const float*)d_in[3];
    const float* rel      = (const float*)d_in[4];
    const float* W_left   = (const float*)d_in[5];
    const float* b_left   = (const float*)d_in[6];
    const float* W_right  = (const float*)d_in[7];
    const float* b_right  = (const float*)d_in[8];
    const float* W_center = (const float*)d_in[9];
    const float* b_center = (const float*)d_in[10];
    const float* W_step   = (const float*)d_in[11];
    const float* b_step   = (const float*)d_in[12];
    const int* query_idx  = (const int*)d_in[13];
    const int* idx_i      = (const int*)d_in[14];
    const int* idx_j      = (const int*)d_in[15];
    const int* max_edges  = (n_in >= 17) ? (const int*)d_in[16] : nullptr;

    int NN = in_sizes[0];
    int E  = in_sizes[13];
    int NQ = in_sizes[2] / D;

    float* out_score = (float*)d_out;
    float* out_rep   = (float*)d_out + NN;

    void* p;
    cudaGetSymbolAddress(&p, g_Pnode);  float* Pnode  = (float*)p;
    cudaGetSymbolAddress(&p, g_Prel);   float* Prel   = (float*)p;
    cudaGetSymbolAddress(&p, g_R1);     float* R1buf  = (float*)p;
    cudaGetSymbolAddress(&p, g_R);      float* Rbuf   = (float*)p;
    cudaGetSymbolAddress(&p, g_Wnode);  float* Wnode  = (float*)p;
    cudaGetSymbolAddress(&p, g_Wrel);   float* Wrel   = (float*)p;
    cudaGetSymbolAddress(&p, g_newrep); float* newrep = (float*)p;

    const int T = 256;
    // --- init state ---
    kzero_f<<<(NN + T - 1) / T, T>>>(out_score, NN);
    {
        int mx = NN > E ? NN : E;
        if (NQ * 256 > mx) mx = NQ * 256;
        k_zero_state<<<(mx + T - 1) / T, T>>>(NN, E, NQ);
    }
    // --- weight prep + per-query precombine ---
    k_repack<<<(512 * D + T - 1) / T, T>>>(W_left, W_right);
    k_qcomb<<<(NQ * 256 + T - 1) / T, T>>>(qsrc, qrel, W_left, b_left, W_right, b_right, NQ);
    // --- dense GEMMs ---
    gemm_nt<false><<<dim3(4, (NN + 127) / 128), T>>>(node_rep, Wnode, Pnode, nullptr, NN, 512, 128);
    gemm_nt<false><<<dim3(4, (E + 127) / 128), T>>>(rel, Wrel, Prel, nullptr, E, 512, 128);
    // --- per-edge assemble (gathers + leaky) ---
    k_assemble<<<((size_t)E * 64 + T - 1) / T, T>>>(idx_i, idx_j, query_idx, E);
    // --- center GEMM ---
    gemm_nt<false><<<dim3(2, (E + 127) / 128), T>>>(R1buf, W_center, Rbuf, nullptr, E, 256, 256);
    // --- logits + segment softmax ---
    k_logits<<<((size_t)E * 32 + T - 1) / T, T>>>(b_center, idx_i, E);
    k_ex<<<(E + T - 1) / T, T>>>(idx_i, E);
    k_score<<<(E + T - 1) / T, T>>>(idx_i, visited, E);
    // --- per-query exact top-k (radix select on float bits) ---
    k_init_select<<<(NQ + T - 1) / T, T>>>(max_edges, NQ);
    int shifts[4] = {24, 16, 8, 0};
    for (int pp = 0; pp < 4; pp++) {
        k_hist<<<(E + T - 1) / T, T>>>(query_idx, E, shifts[pp]);
        k_scan<<<1, 256>>>(shifts[pp], NQ);
    }
    k_eq_gather<<<(E + T - 1) / T, T>>>(query_idx, E);
    k_eq_resolve<<<NQ, 128>>>(NQ);
    // --- aggregation ---
    cudaMemcpyAsync(newrep, node_rep, (size_t)NN * D * sizeof(float),
                    cudaMemcpyDeviceToDevice, 0);
    k_aggregate<<<((size_t)E * 32 + T - 1) / T, T>>>(node_rep, query_idx, idx_i, idx_j, out_score, E);
    // --- step GEMM with bias + leaky epilogue ---
    gemm_nt<true><<<dim3(1, (NN + 127) / 128), T>>>(newrep, W_step, out_rep, b_step, NN, 128, 128);
    (void)out_size;
}

// round 6
// speedup vs baseline: 1.0255x; 1.0255x over previous
#include <cuda_runtime.h>
#include <cstdint>
#include <math.h>

#define D 128
#define NMAX 100352
#define EMAX 131072
#define NQMAX 128
#define EQCAP 1024

// ---------------- static scratch (allocation-free rule) ----------------
__device__ float    g_Wnode[512 * D];           // rows: Wl[:, :128] ; Wr[:, :128]
__device__ float    g_Wrel [512 * D];           // rows: Wl[:,128:256] ; Wr[:,128:256]
__device__ float    g_Wq   [512 * 256];         // rows: Wl[:,256:512] ; Wr[:,256:512]
__device__ float    g_Qin  [NQMAX * 256];       // [qs | qr]
__device__ float    g_Qc   [NQMAX * 512];       // query combined (pre-bias)
__device__ float    g_Pnode[NMAX * 512];
__device__ float    g_Prel [EMAX * 512];
__device__ float    g_L  [EMAX * 256];
__device__ float    g_R1 [EMAX * 256];
__device__ float    g_R  [EMAX * 256];
__device__ float    g_logits[EMAX];
__device__ float    g_ex[EMAX];
__device__ float    g_attn[EMAX];
__device__ float    g_scoreE[EMAX];
__device__ unsigned g_ukey[EMAX];
__device__ unsigned g_segmax[NMAX];
__device__ float    g_denom[NMAX];
__device__ float    g_newrep[NMAX * D];
__device__ unsigned g_hist[NQMAX * 256];
__device__ unsigned g_prefix[NQMAX];
__device__ int      g_krem[NQMAX];
__device__ int      g_keepall[NQMAX];
__device__ int      g_eqcnt[NQMAX];
__device__ int      g_eqlist[NQMAX * EQCAP];
__device__ int      g_eqkeep[EMAX];

__device__ __forceinline__ float leaky(float x) { return x > 0.f ? x : 0.01f * x; }
__device__ __forceinline__ unsigned f2mono(float f) {
    unsigned b = __float_as_uint(f);
    return (b & 0x80000000u) ? ~b : (b | 0x80000000u);
}
__device__ __forceinline__ float mono2f(unsigned u) {
    return (u & 0x80000000u) ? __uint_as_float(u & 0x7fffffffu) : __uint_as_float(~u);
}
__device__ __forceinline__ uint32_t smem_u32(const void* p) {
    uint32_t a;
    asm("{ .reg .u64 t; cvta.to.shared.u64 t, %1; cvt.u32.u64 %0, t; }" : "=r"(a) : "l"(p));
    return a;
}
__device__ __forceinline__ void split_tf32(float v, uint32_t& hi, uint32_t& lo) {
    asm("cvt.rna.tf32.f32 %0, %1;" : "=r"(hi) : "f"(v));
    float r = v - __uint_as_float(hi);
    asm("cvt.rna.tf32.f32 %0, %1;" : "=r"(lo) : "f"(r));
}
__device__ __forceinline__ void mma_tf32(float* d, const uint32_t* a, const uint32_t* b) {
    asm volatile(
        "mma.sync.aligned.m16n8k8.row.col.f32.tf32.tf32.f32 "
        "{%0,%1,%2,%3}, {%4,%5,%6,%7}, {%8,%9}, {%0,%1,%2,%3};"
        : "+f"(d[0]), "+f"(d[1]), "+f"(d[2]), "+f"(d[3])
        : "r"(a[0]), "r"(a[1]), "r"(a[2]), "r"(a[3]), "r"(b[0]), "r"(b[1]));
}

// ================= 3xTF32 mma.sync GEMM: C[M,N] = A[M,K] @ B[N,K]^T (+bias,leaky) =================
// CTA tile 128x128, BK=32, 2-stage cp.async, 8 warps (warp tile 64x32 via 4x4 m16n8k8)
#define GPAD 36
#define GEMM_SMEM_BYTES (4 * 128 * GPAD * 4)   // 2 stages x (A + B) x 128 x 36 floats
template <bool BIAS_LEAKY>
__global__ __launch_bounds__(256) void gemm_mma(const float* __restrict__ A,
                                                const float* __restrict__ B,
                                                float* __restrict__ C,
                                                const float* __restrict__ bias,
                                                int M, int N, int K) {
    extern __shared__ __align__(16) float smem[];
    float* As = smem;                          // [2][128][GPAD]
    float* Bs = smem + 2 * 128 * GPAD;         // [2][128][GPAD]
    const int tid = threadIdx.x;
    const int lane = tid & 31;
    const int wid = tid >> 5;
    const int gid = lane >> 2;    // 0..7
    const int tig = lane & 3;     // 0..3
    const int wm = wid & 1;       // 0..1 -> 64 rows each
    const int wn = wid >> 1;      // 0..3 -> 32 cols each
    const int bm = blockIdx.y * 128, bn = blockIdx.x * 128;

    float acc[4][4][4];
#pragma unroll
    for (int mt = 0; mt < 4; mt++)
#pragma unroll
        for (int nt = 0; nt < 4; nt++)
#pragma unroll
            for (int r = 0; r < 4; r++) acc[mt][nt][r] = 0.f;

#define ISSUE_STAGE(stage, kc)                                                          \
    do {                                                                                \
        _Pragma("unroll")                                                               \
        for (int ch = tid; ch < 2048; ch += 256) {                                      \
            int isB = ch >> 10;                                                         \
            int c2 = ch & 1023;                                                         \
            int row = c2 >> 3, seg = c2 & 7;                                            \
            const float* src = (isB ? B + (size_t)(bn + row) * K                        \
                                    : A + (size_t)(bm + row) * K) + (kc) + seg * 4;     \
            float* dstp = (isB ? Bs : As) + (stage) * 128 * GPAD + row * GPAD + seg * 4;\
            uint32_t dst = smem_u32(dstp);                                              \
            int sz = (isB || (bm + row) < M) ? 16 : 0;                                  \
            asm volatile("cp.async.cg.shared.global [%0], [%1], 16, %2;"                \
                         :: "r"(dst), "l"(src), "r"(sz));                               \
        }                                                                               \
        asm volatile("cp.async.commit_group;" ::: "memory");                            \
    } while (0)

    const int nch = K >> 5;
    ISSUE_STAGE(0, 0);

    for (int c = 0; c < nch; c++) {
        if (c + 1 < nch) {
            ISSUE_STAGE((c + 1) & 1, (c + 1) << 5);
            asm volatile("cp.async.wait_group 1;" ::: "memory");
        } else {
            asm volatile("cp.async.wait_group 0;" ::: "memory");
        }
        __syncthreads();

        const float* as = As + (c & 1) * 128 * GPAD + (wm * 64) * GPAD;
        const float* bs = Bs + (c & 1) * 128 * GPAD + (wn * 32) * GPAD;
#pragma unroll
        for (int k0 = 0; k0 < 32; k0 += 8) {
            uint32_t ah[4][4], al[4][4], bh[4][2], bl[4][2];
#pragma unroll
            for (int mt = 0; mt < 4; mt++) {
                float v0 = as[(mt * 16 + gid) * GPAD + k0 + tig];
                float v1 = as[(mt * 16 + gid + 8) * GPAD + k0 + tig];
                float v2 = as[(mt * 16 + gid) * GPAD + k0 + tig + 4];
                float v3 = as[(mt * 16 + gid + 8) * GPAD + k0 + tig + 4];
                split_tf32(v0, ah[mt][0], al[mt][0]);
                split_tf32(v1, ah[mt][1], al[mt][1]);
                split_tf32(v2, ah[mt][2], al[mt][2]);
                split_tf32(v3, ah[mt][3], al[mt][3]);
            }
#pragma unroll
            for (int nt = 0; nt < 4; nt++) {
                float u0 = bs[(nt * 8 + gid) * GPAD + k0 + tig];
                float u1 = bs[(nt * 8 + gid) * GPAD + k0 + tig + 4];
                split_tf32(u0, bh[nt][0], bl[nt][0]);
                split_tf32(u1, bh[nt][1], bl[nt][1]);
            }
#pragma unroll
            for (int mt = 0; mt < 4; mt++)
#pragma unroll
                for (int nt = 0; nt < 4; nt++) {
                    mma_tf32(acc[mt][nt], ah[mt], bh[nt]);
                    mma_tf32(acc[mt][nt], ah[mt], bl[nt]);
                    mma_tf32(acc[mt][nt], al[mt], bh[nt]);
                }
        }
        __syncthreads();
    }

    // ---- epilogue ----
#pragma unroll
    for (int mt = 0; mt < 4; mt++) {
        int row0 = bm + wm * 64 + mt * 16 + gid;
#pragma unroll
        for (int nt = 0; nt < 4; nt++) {
            int col = bn + wn * 32 + nt * 8 + tig * 2;
            float d0 = acc[mt][nt][0], d1 = acc[mt][nt][1];
            float d2 = acc[mt][nt][2], d3 = acc[mt][nt][3];
            if (BIAS_LEAKY) {
                float b0 = bias[col], b1 = bias[col + 1];
                d0 = leaky(d0 + b0); d1 = leaky(d1 + b1);
                d2 = leaky(d2 + b0); d3 = leaky(d3 + b1);
            }
            if (row0 < M) *(float2*)(C + (size_t)row0 * N + col) = make_float2(d0, d1);
            if (row0 + 8 < M) *(float2*)(C + (size_t)(row0 + 8) * N + col) = make_float2(d2, d3);
        }
    }
}

// ---------------- misc small kernels ----------------
__global__ void kzero_f(float* p, int n) {
    int i = blockIdx.x * blockDim.x + threadIdx.x;
    if (i < n) p[i] = 0.f;
}
__global__ void k_zero_state(int NN, int E, int NQ) {
    int t = blockIdx.x * blockDim.x + threadIdx.x;
    if (t < NN) { g_segmax[t] = 0u; g_denom[t] = 0.f; }
    if (t < E)  g_eqkeep[t] = 0;
    if (t < NQ * 256) g_hist[t] = 0u;
}

// weight repack: route W_left/W_right columns into the three B matrices
__global__ void k_prep(const float* __restrict__ Wl, const float* __restrict__ Wr) {
    int t = blockIdx.x * blockDim.x + threadIdx.x;
    if (t >= 512 * 512) return;
    int j = t >> 9, k = t & 511;
    float v = (j < 256) ? Wl[(size_t)j * 512 + k] : Wr[(size_t)(j - 256) * 512 + k];
    if (k < 128)      g_Wnode[j * 128 + k] = v;
    else if (k < 256) g_Wrel[j * 128 + (k - 128)] = v;
    else              g_Wq[j * 256 + (k - 256)] = v;
}
__global__ void k_qin(const float* __restrict__ qs, const float* __restrict__ qr, int NQ) {
    int t = blockIdx.x * blockDim.x + threadIdx.x;
    if (t >= NQ * 256) return;
    int q = t >> 8, k = t & 255;
    g_Qin[t] = (k < 128) ? qs[q * 128 + k] : qr[q * 128 + (k - 128)];
}

// edge assembly: L = leaky(Pnode[i,c] + Prel[e,c] + Qc[q,c] + bl[c]);  R1 similar
__global__ void k_assemble(const int* __restrict__ idx_i, const int* __restrict__ idx_j,
                           const int* __restrict__ qidx,
                           const float* __restrict__ bl, const float* __restrict__ br, int E) {
    int t = blockIdx.x * blockDim.x + threadIdx.x;
    int e = t >> 6;
    if (e >= E) return;
    int c = (t & 63) * 4;
    int i = idx_i[e], j = idx_j[e], q = qidx[e];

    float4 pl = *(const float4*)(g_Pnode + (size_t)i * 512 + c);
    float4 rl = *(const float4*)(g_Prel + (size_t)e * 512 + c);
    float4 ql = *(const float4*)(g_Qc + (size_t)q * 512 + c);
    float4 bb = *(const float4*)(bl + c);
    float4 o;
    o.x = leaky(pl.x + rl.x + ql.x + bb.x);
    o.y = leaky(pl.y + rl.y + ql.y + bb.y);
    o.z = leaky(pl.z + rl.z + ql.z + bb.z);
    o.w = leaky(pl.w + rl.w + ql.w + bb.w);
    *(float4*)(g_L + (size_t)e * 256 + c) = o;

    float4 pr = *(const float4*)(g_Pnode + (size_t)j * 512 + 256 + c);
    float4 rr = *(const float4*)(g_Prel + (size_t)e * 512 + 256 + c);
    float4 qq = *(const float4*)(g_Qc + (size_t)q * 512 + 256 + c);
    float4 b2 = *(const float4*)(br + c);
    float4 o2;
    o2.x = leaky(pr.x + rr.x + qq.x + b2.x);
    o2.y = leaky(pr.y + rr.y + qq.y + b2.y);
    o2.z = leaky(pr.z + rr.z + qq.z + b2.z);
    o2.w = leaky(pr.w + rr.w + qq.w + b2.w);
    *(float4*)(g_R1 + (size_t)e * 256 + c) = o2;
}

// logits = sum_n L[e,n]*(R[e,n]+bc[n]); atomic seg-max
__global__ void k_logits(const float* __restrict__ bc, const int* __restrict__ idx_i, int E) {
    int gw = (blockIdx.x * blockDim.x + threadIdx.x) >> 5;
    int lane = threadIdx.x & 31;
    if (gw >= E) return;
    const float* Lr = g_L + (size_t)gw * 256;
    const float* Rr = g_R + (size_t)gw * 256;
    float s = 0.f;
    int c = lane * 4;
#pragma unroll
    for (int h = 0; h < 2; h++, c += 128) {
        float4 l = *(const float4*)(Lr + c);
        float4 r = *(const float4*)(Rr + c);
        float4 b = *(const float4*)(bc + c);
        s = fmaf(l.x, r.x + b.x, s);
        s = fmaf(l.y, r.y + b.y, s);
        s = fmaf(l.z, r.z + b.z, s);
        s = fmaf(l.w, r.w + b.w, s);
    }
#pragma unroll
    for (int o = 16; o; o >>= 1) s += __shfl_xor_sync(0xffffffffu, s, o);
    if (lane == 0) {
        g_logits[gw] = s;
        atomicMax(&g_segmax[idx_i[gw]], f2mono(s));
    }
}
__global__ void k_ex(const int* __restrict__ idx_i, int E) {
    int e = blockIdx.x * blockDim.x + threadIdx.x;
    if (e >= E) return;
    int i = idx_i[e];
    float m = mono2f(g_segmax[i]);
    float ex = expf(g_logits[e] - m);
    g_ex[e] = ex;
    atomicAdd(&g_denom[i], ex);
}
__global__ void k_score(const int* __restrict__ idx_i, const float* __restrict__ visited, int E) {
    int e = blockIdx.x * blockDim.x + threadIdx.x;
    if (e >= E) return;
    int i = idx_i[e];
    float a = g_ex[e] / g_denom[i];
    g_attn[e] = a;
    float sc = a * visited[i];
    g_scoreE[e] = sc;
    g_ukey[e] = __float_as_uint(sc);
}

// ---------------- top-k radix select ----------------
__global__ void k_init_select(const int* __restrict__ max_edges, int NQ) {
    int q = blockIdx.x * blockDim.x + threadIdx.x;
    if (q < NQ) {
        g_krem[q] = max_edges ? *max_edges : 1024;
        g_prefix[q] = 0u;
        g_keepall[q] = 0;
        g_eqcnt[q] = 0;
    }
}
__global__ void k_hist(const int* __restrict__ qidx, int E, int shift) {
    int e = blockIdx.x * blockDim.x + threadIdx.x;
    if (e >= E) return;
    int q = qidx[e];
    if (g_keepall[q]) return;
    unsigned u = g_ukey[e];
    if (shift < 24 && ((u >> (shift + 8)) != (g_prefix[q] >> (shift + 8)))) return;
    atomicAdd(&g_hist[(q << 8) + ((u >> shift) & 255u)], 1u);
}
__global__ void k_scan(int shift, int NQ) {
    int q = threadIdx.x;
    if (q < NQ && !g_keepall[q]) {
        unsigned kr = (unsigned)g_krem[q];
        unsigned c = 0;
        int found = 0;
        for (int b = 255; b >= 0; b--) {
            unsigned h = g_hist[(q << 8) + b];
            if (c + h >= kr) {
                g_prefix[q] |= ((unsigned)b) << shift;
                g_krem[q] = (int)(kr - c);
                found = 1;
                break;
            }
            c += h;
        }
        if (!found) g_keepall[q] = 1;
    }
    __syncthreads();
    for (int t = threadIdx.x; t < NQ * 256; t += blockDim.x) g_hist[t] = 0u;
}
__global__ void k_eq_gather(const int* __restrict__ qidx, int E) {
    int e = blockIdx.x * blockDim.x + threadIdx.x;
    if (e >= E) return;
    int q = qidx[e];
    if (g_keepall[q]) return;
    if (g_ukey[e] == g_prefix[q]) {
        int p = atomicAdd(&g_eqcnt[q], 1);
        if (p < EQCAP) g_eqlist[q * EQCAP + p] = e;
    }
}
__global__ void k_eq_resolve(int NQ) {
    int q = blockIdx.x;
    if (q >= NQ || g_keepall[q]) return;
    int n = min(g_eqcnt[q], EQCAP);
    int keq = g_krem[q];
    for (int t = threadIdx.x; t < n; t += blockDim.x) {
        int me = g_eqlist[q * EQCAP + t];
        if (n <= keq) { g_eqkeep[me] = 1; continue; }
        int cnt = 0;
        for (int jj = 0; jj < n; jj++) cnt += (g_eqlist[q * EQCAP + jj] < me);
        if (cnt < keq) g_eqkeep[me] = 1;
    }
}

// ---------------- pruned aggregation ----------------
__global__ void k_aggregate(const float* __restrict__ node_rep, const int* __restrict__ qidx,
                            const int* __restrict__ idx_i, const int* __restrict__ idx_j,
                            float* __restrict__ out_score, int E) {
    int w = (blockIdx.x * blockDim.x + threadIdx.x) >> 5;
    int lane = threadIdx.x & 31;
    if (w >= E) return;
    int q = qidx[w];
    bool keep = g_keepall[q] || (g_ukey[w] > g_prefix[q]) || g_eqkeep[w];
    if (!keep) return;
    int i = idx_i[w], j = idx_j[w];
    if (lane == 0) atomicAdd(out_score + j, g_scoreE[w]);
    float a = g_attn[w];
    float4 h = *(const float4*)(node_rep + (size_t)i * D + lane * 4);
#if __CUDA_ARCH__ >= 900
    atomicAdd((float4*)(g_newrep + (size_t)j * D + lane * 4),
              make_float4(a * h.x, a * h.y, a * h.z, a * h.w));
#else
    float* dst = g_newrep + (size_t)j * D + lane * 4;
    atomicAdd(dst + 0, a * h.x);
    atomicAdd(dst + 1, a * h.y);
    atomicAdd(dst + 2, a * h.z);
    atomicAdd(dst + 3, a * h.w);
#endif
}

// ---------------- launch ----------------
extern "C" void kernel_launch(void* const* d_in, const int* in_sizes, int n_in,
                              void* d_out, int out_size) {
    const float* visited  = (const float*)d_in[0];
    const float* node_rep = (const float*)d_in[1];
    const float* qsrc     = (const float*)d_in[2];
    const float* qrel     = (const float*)d_in[3];
    const float* rel      = (const float*)d_in[4];
    const float* W_left   = (const float*)d_in[5];
    const float* b_left   = (const float*)d_in[6];
    const float* W_right  = (const float*)d_in[7];
    const float* b_right  = (const float*)d_in[8];
    const float* W_center = (const float*)d_in[9];
    const float* b_center = (const float*)d_in[10];
    const float* W_step   = (const float*)d_in[11];
    const float* b_step   = (const float*)d_in[12];
    const int* query_idx  = (const int*)d_in[13];
    const int* idx_i      = (const int*)d_in[14];
    const int* idx_j      = (const int*)d_in[15];
    const int* max_edges  = (n_in >= 17) ? (const int*)d_in[16] : nullptr;

    int NN = in_sizes[0];
    int E  = in_sizes[13];
    int NQ = in_sizes[2] / D;

    float* out_score = (float*)d_out;
    float* out_rep   = (float*)d_out + NN;

    void* p;
    cudaGetSymbolAddress(&p, g_Pnode);  float* Pnode  = (float*)p;
    cudaGetSymbolAddress(&p, g_Prel);   float* Prel   = (float*)p;
    cudaGetSymbolAddress(&p, g_R1);     float* R1buf  = (float*)p;
    cudaGetSymbolAddress(&p, g_R);      float* Rbuf   = (float*)p;
    cudaGetSymbolAddress(&p, g_Wnode);  float* Wnode  = (float*)p;
    cudaGetSymbolAddress(&p, g_Wrel);   float* Wrel   = (float*)p;
    cudaGetSymbolAddress(&p, g_Wq);     float* Wq     = (float*)p;
    cudaGetSymbolAddress(&p, g_Qin);    float* Qin    = (float*)p;
    cudaGetSymbolAddress(&p, g_Qc);     float* Qc     = (float*)p;
    cudaGetSymbolAddress(&p, g_newrep); float* newrep = (float*)p;

    static int smem_set = 0;
    if (!smem_set) {
        cudaFuncSetAttribute(gemm_mma<false>, cudaFuncAttributeMaxDynamicSharedMemorySize, GEMM_SMEM_BYTES);
        cudaFuncSetAttribute(gemm_mma<true>,  cudaFuncAttributeMaxDynamicSharedMemorySize, GEMM_SMEM_BYTES);
        smem_set = 1;
    }

    const int T = 256;
    // --- init state ---
    kzero_f<<<(NN + T - 1) / T, T>>>(out_score, NN);
    {
        int mx = NN > E ? NN : E;
        if (NQ * 256 > mx) mx = NQ * 256;
        k_zero_state<<<(mx + T - 1) / T, T>>>(NN, E, NQ);
    }
    // --- weight prep + query precombine ---
    k_prep<<<(512 * 512 + T - 1) / T, T>>>(W_left, W_right);
    k_qin<<<(NQ * 256 + T - 1) / T, T>>>(qsrc, qrel, NQ);
    gemm_mma<false><<<dim3(4, 1), T, GEMM_SMEM_BYTES>>>(Qin, Wq, Qc, nullptr, NQ, 512, 256);
    // --- big GEMMs on tensor pipe ---
    gemm_mma<false><<<dim3(4, (NN + 127) / 128), T, GEMM_SMEM_BYTES>>>(node_rep, Wnode, Pnode, nullptr, NN, 512, 128);
    gemm_mma<false><<<dim3(4, (E + 127) / 128), T, GEMM_SMEM_BYTES>>>(rel, Wrel, Prel, nullptr, E, 512, 128);
    // --- per-edge assemble ---
    k_assemble<<<((size_t)E * 64 + T - 1) / T, T>>>(idx_i, idx_j, query_idx, b_left, b_right, E);
    // --- center GEMM ---
    gemm_mma<false><<<dim3(2, (E + 127) / 128), T, GEMM_SMEM_BYTES>>>(R1buf, W_center, Rbuf, nullptr, E, 256, 256);
    // --- logits + segment softmax ---
    k_logits<<<((size_t)E * 32 + T - 1) / T, T>>>(b_center, idx_i, E);
    k_ex<<<(E + T - 1) / T, T>>>(idx_i, E);
    k_score<<<(E + T - 1) / T, T>>>(idx_i, visited, E);
    // --- per-query exact top-k ---
    k_init_select<<<(NQ + T - 1) / T, T>>>(max_edges, NQ);
    int shifts[4] = {24, 16, 8, 0};
    for (int pp = 0; pp < 4; pp++) {
        k_hist<<<(E + T - 1) / T, T>>>(query_idx, E, shifts[pp]);
        k_scan<<<1, 256>>>(shifts[pp], NQ);
    }
    k_eq_gather<<<(E + T - 1) / T, T>>>(query_idx, E);
    k_eq_resolve<<<NQ, 128>>>(NQ);
    // --- aggregation ---
    cudaMemcpyAsync(newrep, node_rep, (size_t)NN * D * sizeof(float),
                    cudaMemcpyDeviceToDevice, 0);
    k_aggregate<<<((size_t)E * 32 + T - 1) / T, T>>>(node_rep, query_idx, idx_i, idx_j, out_score, E);
    // --- step GEMM with bias + leaky ---
    gemm_mma<true><<<dim3(1, (NN + 127) / 128), T, GEMM_SMEM_BYTES>>>(newrep, W_step, out_rep, b_step, NN, 128, 128);
    (void)out_size;
}

// round 7
// speedup vs baseline: 1.8672x; 1.8209x over previous
#include <cuda_runtime.h>
#include <cuda_fp16.h>
#include <cstdint>
#include <math.h>

#define D 128
#define NMAX 100352
#define EMAX 131072
#define NQMAX 128
#define EQCAP 1024

// ---------------- static scratch (allocation-free rule) ----------------
__device__ float    g_Qc   [NQMAX * 512];       // query combined (pre-bias)
__device__ float    g_Pnode[NMAX * 512];
__device__ float    g_Prel [EMAX * 512];
__device__ float    g_L  [EMAX * 256];
__device__ float    g_R  [EMAX * 256];
__device__ float    g_logits[EMAX];
__device__ float    g_ex[EMAX];
__device__ float    g_attn[EMAX];
__device__ float    g_scoreE[EMAX];
__device__ unsigned g_ukey[EMAX];
__device__ unsigned g_segmax[NMAX];
__device__ float    g_denom[NMAX];
__device__ float    g_newrep[NMAX * D];
__device__ unsigned g_hist[NQMAX * 256];
__device__ unsigned g_prefix[NQMAX];
__device__ int      g_krem[NQMAX];
__device__ int      g_keepall[NQMAX];
__device__ int      g_eqcnt[NQMAX];
__device__ int      g_eqlist[NQMAX * EQCAP];
__device__ int      g_eqkeep[EMAX];

// split fp16 operand buffers (hi/lo)
__device__ __align__(128) __half g_WnodeH[512 * 128], g_WnodeL[512 * 128];
__device__ __align__(128) __half g_WrelH [512 * 128], g_WrelL [512 * 128];
__device__ __align__(128) __half g_WqH   [512 * 256], g_WqL   [512 * 256];
__device__ __align__(128) __half g_WcH   [256 * 256], g_WcL   [256 * 256];
__device__ __align__(128) __half g_WsH   [128 * 128], g_WsL   [128 * 128];
__device__ __align__(128) __half g_QinH  [NQMAX * 256], g_QinL[NQMAX * 256];
__device__ __align__(128) __half g_NodeH [NMAX * 128], g_NodeL[NMAX * 128];
__device__ __align__(128) __half g_RelH  [EMAX * 128], g_RelL [EMAX * 128];
__device__ __align__(128) __half g_R1H   [EMAX * 256], g_R1L  [EMAX * 256];
__device__ __align__(128) __half g_NrH   [NMAX * 128], g_NrL  [NMAX * 128];

__device__ __forceinline__ float leaky(float x) { return x > 0.f ? x : 0.01f * x; }
__device__ __forceinline__ unsigned f2mono(float f) {
    unsigned b = __float_as_uint(f);
    return (b & 0x80000000u) ? ~b : (b | 0x80000000u);
}
__device__ __forceinline__ float mono2f(unsigned u) {
    return (u & 0x80000000u) ? __uint_as_float(u & 0x7fffffffu) : __uint_as_float(~u);
}
__device__ __forceinline__ uint32_t smem_u32(const void* p) {
    uint32_t a;
    asm("{ .reg .u64 t; cvta.to.shared.u64 t, %1; cvt.u32.u64 %0, t; }" : "=r"(a) : "l"(p));
    return a;
}
__device__ __forceinline__ void split_h(float v, __half& h, __half& l) {
    h = __float2half_rn(v);
    l = __float2half_rn(v - __half2float(h));
}
__device__ __forceinline__ void ldsm4(uint32_t* r, uint32_t addr) {
    asm volatile("ldmatrix.sync.aligned.m8n8.x4.shared.b16 {%0,%1,%2,%3}, [%4];"
                 : "=r"(r[0]), "=r"(r[1]), "=r"(r[2]), "=r"(r[3]) : "r"(addr));
}
__device__ __forceinline__ void mma_f16(float* d, const uint32_t* a, const uint32_t* b) {
    asm volatile(
        "mma.sync.aligned.m16n8k16.row.col.f32.f16.f16.f32 "
        "{%0,%1,%2,%3}, {%4,%5,%6,%7}, {%8,%9}, {%0,%1,%2,%3};"
        : "+f"(d[0]), "+f"(d[1]), "+f"(d[2]), "+f"(d[3])
        : "r"(a[0]), "r"(a[1]), "r"(a[2]), "r"(a[3]), "r"(b[0]), "r"(b[1]));
}

// ================= fp16 3-pass split GEMM: C[M,N] = A[M,K] @ B[N,K]^T (+bias,leaky) =================
// CTA tile 128x128, BK=32, 2-stage cp.async on pre-split fp16 operands, 8 warps (64x32 warp tile)
#define ROWH 40                         // smem row stride in halves (80B, conflict-free for ldmatrix)
#define TILE_H (128 * ROWH)             // halves per tile
#define STAGE_H (4 * TILE_H)            // Ah, Al, Bh, Bl
#define GEMM_SMEM_BYTES (2 * STAGE_H * 2)  // 81920 bytes
template <bool BIAS_LEAKY>
__global__ __launch_bounds__(256) void gemm_f16(const __half* __restrict__ Ah,
                                                const __half* __restrict__ Al,
                                                const __half* __restrict__ Bh,
                                                const __half* __restrict__ Bl,
                                                float* __restrict__ C,
                                                const float* __restrict__ bias,
                                                int M, int N, int K) {
    extern __shared__ __align__(128) __half sm[];
    const int tid = threadIdx.x, lane = tid & 31, wid = tid >> 5;
    const int wm = wid & 1, wn = wid >> 1;
    const int bm = blockIdx.y * 128, bn = blockIdx.x * 128;
    const int rl = lane & 7, q = lane >> 3;

    float acc[4][4][4];
#pragma unroll
    for (int mt = 0; mt < 4; mt++)
#pragma unroll
        for (int nt = 0; nt < 4; nt++)
#pragma unroll
            for (int r = 0; r < 4; r++) acc[mt][nt][r] = 0.f;

#define LOAD_STAGE(st, kc)                                                               \
    do {                                                                                 \
        _Pragma("unroll")                                                                \
        for (int i = 0; i < 8; i++) {                                                    \
            int ch = tid + i * 256;                                                      \
            int tile = ch >> 9, r = (ch >> 2) & 127, seg = ch & 3;                       \
            const __half* src;                                                           \
            int sz = 16;                                                                 \
            if (tile < 2) {                                                              \
                int row = bm + r;                                                        \
                int rc = row < M ? row : 0;                                              \
                sz = row < M ? 16 : 0;                                                   \
                src = (tile == 0 ? Ah : Al) + (size_t)rc * K + (kc) + seg * 8;           \
            } else {                                                                     \
                int row = bn + r;                                                        \
                src = (tile == 2 ? Bh : Bl) + (size_t)row * K + (kc) + seg * 8;          \
            }                                                                            \
            uint32_t dst = smem_u32(sm + (st)*STAGE_H + tile * TILE_H + r * ROWH + seg * 8); \
            asm volatile("cp.async.cg.shared.global [%0], [%1], 16, %2;"                 \
                         :: "r"(dst), "l"(src), "r"(sz));                                \
        }                                                                                \
        asm volatile("cp.async.commit_group;" ::: "memory");                             \
    } while (0)

    const int nch = K >> 5;
    LOAD_STAGE(0, 0);

    for (int c = 0; c < nch; c++) {
        if (c + 1 < nch) {
            LOAD_STAGE((c + 1) & 1, (c + 1) << 5);
            asm volatile("cp.async.wait_group 1;" ::: "memory");
        } else {
            asm volatile("cp.async.wait_group 0;" ::: "memory");
        }
        __syncthreads();

        const __half* base = sm + (c & 1) * STAGE_H;
        uint32_t aAh = smem_u32(base);
        uint32_t aAl = smem_u32(base + TILE_H);
        uint32_t aBh = smem_u32(base + 2 * TILE_H);
        uint32_t aBl = smem_u32(base + 3 * TILE_H);

#pragma unroll
        for (int ks = 0; ks < 2; ks++) {
            uint32_t ah[4][4], al[4][4], bh[4][2], bl[4][2];
#pragma unroll
            for (int mt = 0; mt < 4; mt++) {
                // A frag: row = (q&1)*8 + rl, k-half = (q>>1)*8
                uint32_t off = ((wm * 64 + mt * 16 + (q & 1) * 8 + rl) * ROWH +
                                ks * 16 + (q >> 1) * 8) * 2;
                ldsm4(ah[mt], aAh + off);
                ldsm4(al[mt], aAl + off);
            }
#pragma unroll
            for (int p = 0; p < 2; p++) {
                // B frag pair: n = (q>>1)*8 + rl, k-half = (q&1)*8
                uint32_t off = ((wn * 32 + p * 16 + (q >> 1) * 8 + rl) * ROWH +
                                ks * 16 + (q & 1) * 8) * 2;
                uint32_t t[4];
                ldsm4(t, aBh + off);
                bh[2 * p][0] = t[0]; bh[2 * p][1] = t[1];
                bh[2 * p + 1][0] = t[2]; bh[2 * p + 1][1] = t[3];
                ldsm4(t, aBl + off);
                bl[2 * p][0] = t[0]; bl[2 * p][1] = t[1];
                bl[2 * p + 1][0] = t[2]; bl[2 * p + 1][1] = t[3];
            }
#pragma unroll
            for (int mt = 0; mt < 4; mt++)
#pragma unroll
                for (int nt = 0; nt < 4; nt++) {
                    mma_f16(acc[mt][nt], ah[mt], bh[nt]);
                    mma_f16(acc[mt][nt], ah[mt], bl[nt]);
                    mma_f16(acc[mt][nt], al[mt], bh[nt]);
                }
        }
        __syncthreads();
    }

    // ---- epilogue ----
    const int g = lane >> 2, t4 = lane & 3;
#pragma unroll
    for (int mt = 0; mt < 4; mt++) {
        int row0 = bm + wm * 64 + mt * 16 + g;
#pragma unroll
        for (int nt = 0; nt < 4; nt++) {
            int col = bn + wn * 32 + nt * 8 + t4 * 2;
            float d0 = acc[mt][nt][0], d1 = acc[mt][nt][1];
            float d2 = acc[mt][nt][2], d3 = acc[mt][nt][3];
            if (BIAS_LEAKY) {
                float b0 = bias[col], b1 = bias[col + 1];
                d0 = leaky(d0 + b0); d1 = leaky(d1 + b1);
                d2 = leaky(d2 + b0); d3 = leaky(d3 + b1);
            }
            if (row0 < M) *(float2*)(C + (size_t)row0 * N + col) = make_float2(d0, d1);
            if (row0 + 8 < M) *(float2*)(C + (size_t)(row0 + 8) * N + col) = make_float2(d2, d3);
        }
    }
}

// ---------------- misc small kernels ----------------
__global__ void kzero_f(float* p, int n) {
    int i = blockIdx.x * blockDim.x + threadIdx.x;
    if (i < n) p[i] = 0.f;
}
__global__ void k_zero_state(int NN, int E, int NQ) {
    int t = blockIdx.x * blockDim.x + threadIdx.x;
    if (t < NN) { g_segmax[t] = 0u; g_denom[t] = 0.f; }
    if (t < E)  g_eqkeep[t] = 0;
    if (t < NQ * 256) g_hist[t] = 0u;
}

// generic fp32 -> split fp16 (hi/lo), n4 = n/4
__global__ void k_split(const float* __restrict__ src, __half* __restrict__ hi,
                        __half* __restrict__ lo, int n4) {
    int i = blockIdx.x * blockDim.x + threadIdx.x;
    if (i >= n4) return;
    float4 v = ((const float4*)src)[i];
    __half h0, h1, h2, h3, l0, l1, l2, l3;
    split_h(v.x, h0, l0); split_h(v.y, h1, l1);
    split_h(v.z, h2, l2); split_h(v.w, h3, l3);
    ((__half2*)hi)[i * 2 + 0] = __halves2half2(h0, h1);
    ((__half2*)hi)[i * 2 + 1] = __halves2half2(h2, h3);
    ((__half2*)lo)[i * 2 + 0] = __halves2half2(l0, l1);
    ((__half2*)lo)[i * 2 + 1] = __halves2half2(l2, l3);
}

// weight repack + split: route W_left/W_right columns into three split B matrices
__global__ void k_prep(const float* __restrict__ Wl, const float* __restrict__ Wr) {
    int t = blockIdx.x * blockDim.x + threadIdx.x;
    if (t >= 512 * 512) return;
    int j = t >> 9, k = t & 511;
    float v = (j < 256) ? Wl[(size_t)j * 512 + k] : Wr[(size_t)(j - 256) * 512 + k];
    __half h, l;
    split_h(v, h, l);
    if (k < 128)      { g_WnodeH[j * 128 + k] = h;         g_WnodeL[j * 128 + k] = l; }
    else if (k < 256) { g_WrelH[j * 128 + k - 128] = h;    g_WrelL[j * 128 + k - 128] = l; }
    else              { g_WqH[j * 256 + k - 256] = h;      g_WqL[j * 256 + k - 256] = l; }
}
__global__ void k_qin(const float* __restrict__ qs, const float* __restrict__ qr, int NQ) {
    int t = blockIdx.x * blockDim.x + threadIdx.x;
    if (t >= NQ * 256) return;
    int q = t >> 8, k = t & 255;
    float v = (k < 128) ? qs[q * 128 + k] : qr[q * 128 + (k - 128)];
    __half h, l;
    split_h(v, h, l);
    g_QinH[t] = h;
    g_QinL[t] = l;
}

// edge assembly: L = leaky(Pnode[i,c]+Prel[e,c]+Qc[q,c]+bl[c]) (fp32);  R1 -> split fp16
__global__ void k_assemble(const int* __restrict__ idx_i, const int* __restrict__ idx_j,
                           const int* __restrict__ qidx,
                           const float* __restrict__ bl, const float* __restrict__ br, int E) {
    int t = blockIdx.x * blockDim.x + threadIdx.x;
    int e = t >> 6;
    if (e >= E) return;
    int c = (t & 63) * 4;
    int i = idx_i[e], j = idx_j[e], q = qidx[e];

    float4 pl = *(const float4*)(g_Pnode + (size_t)i * 512 + c);
    float4 rle = *(const float4*)(g_Prel + (size_t)e * 512 + c);
    float4 ql = *(const float4*)(g_Qc + (size_t)q * 512 + c);
    float4 bb = *(const float4*)(bl + c);
    float4 o;
    o.x = leaky(pl.x + rle.x + ql.x + bb.x);
    o.y = leaky(pl.y + rle.y + ql.y + bb.y);
    o.z = leaky(pl.z + rle.z + ql.z + bb.z);
    o.w = leaky(pl.w + rle.w + ql.w + bb.w);
    *(float4*)(g_L + (size_t)e * 256 + c) = o;

    float4 pr = *(const float4*)(g_Pnode + (size_t)j * 512 + 256 + c);
    float4 rr = *(const float4*)(g_Prel + (size_t)e * 512 + 256 + c);
    float4 qq = *(const float4*)(g_Qc + (size_t)q * 512 + 256 + c);
    float4 b2 = *(const float4*)(br + c);
    float r0 = leaky(pr.x + rr.x + qq.x + b2.x);
    float r1 = leaky(pr.y + rr.y + qq.y + b2.y);
    float r2 = leaky(pr.z + rr.z + qq.z + b2.z);
    float r3 = leaky(pr.w + rr.w + qq.w + b2.w);
    __half h0, h1, h2, h3, l0, l1, l2, l3;
    split_h(r0, h0, l0); split_h(r1, h1, l1);
    split_h(r2, h2, l2); split_h(r3, h3, l3);
    size_t ofs = (size_t)e * 256 + c;
    *(__half2*)(g_R1H + ofs)     = __halves2half2(h0, h1);
    *(__half2*)(g_R1H + ofs + 2) = __halves2half2(h2, h3);
    *(__half2*)(g_R1L + ofs)     = __halves2half2(l0, l1);
    *(__half2*)(g_R1L + ofs + 2) = __halves2half2(l2, l3);
}

// logits = sum_n L[e,n]*(R[e,n]+bc[n]); atomic seg-max
__global__ void k_logits(const float* __restrict__ bc, const int* __restrict__ idx_i, int E) {
    int gw = (blockIdx.x * blockDim.x + threadIdx.x) >> 5;
    int lane = threadIdx.x & 31;
    if (gw >= E) return;
    const float* Lr = g_L + (size_t)gw * 256;
    const float* Rr = g_R + (size_t)gw * 256;
    float s = 0.f;
    int c = lane * 4;
#pragma unroll
    for (int h = 0; h < 2; h++, c += 128) {
        float4 l = *(const float4*)(Lr + c);
        float4 r = *(const float4*)(Rr + c);
        float4 b = *(const float4*)(bc + c);
        s = fmaf(l.x, r.x + b.x, s);
        s = fmaf(l.y, r.y + b.y, s);
        s = fmaf(l.z, r.z + b.z, s);
        s = fmaf(l.w, r.w + b.w, s);
    }
#pragma unroll
    for (int o = 16; o; o >>= 1) s += __shfl_xor_sync(0xffffffffu, s, o);
    if (lane == 0) {
        g_logits[gw] = s;
        atomicMax(&g_segmax[idx_i[gw]], f2mono(s));
    }
}
__global__ void k_ex(const int* __restrict__ idx_i, int E) {
    int e = blockIdx.x * blockDim.x + threadIdx.x;
    if (e >= E) return;
    int i = idx_i[e];
    float m = mono2f(g_segmax[i]);
    float ex = expf(g_logits[e] - m);
    g_ex[e] = ex;
    atomicAdd(&g_denom[i], ex);
}
__global__ void k_score(const int* __restrict__ idx_i, const float* __restrict__ visited, int E) {
    int e = blockIdx.x * blockDim.x + threadIdx.x;
    if (e >= E) return;
    int i = idx_i[e];
    float a = g_ex[e] / g_denom[i];
    g_attn[e] = a;
    float sc = a * visited[i];
    g_scoreE[e] = sc;
    g_ukey[e] = __float_as_uint(sc);
}

// ---------------- top-k radix select ----------------
__global__ void k_init_select(const int* __restrict__ max_edges, int NQ) {
    int q = blockIdx.x * blockDim.x + threadIdx.x;
    if (q < NQ) {
        g_krem[q] = max_edges ? *max_edges : 1024;
        g_prefix[q] = 0u;
        g_keepall[q] = 0;
        g_eqcnt[q] = 0;
    }
}
__global__ void k_hist(const int* __restrict__ qidx, int E, int shift) {
    int e = blockIdx.x * blockDim.x + threadIdx.x;
    if (e >= E) return;
    int q = qidx[e];
    if (g_keepall[q]) return;
    unsigned u = g_ukey[e];
    if (shift < 24 && ((u >> (shift + 8)) != (g_prefix[q] >> (shift + 8)))) return;
    atomicAdd(&g_hist[(q << 8) + ((u >> shift) & 255u)], 1u);
}
__global__ void k_scan(int shift, int NQ) {
    int q = threadIdx.x;
    if (q < NQ && !g_keepall[q]) {
        unsigned kr = (unsigned)g_krem[q];
        unsigned c = 0;
        int found = 0;
        for (int b = 255; b >= 0; b--) {
            unsigned h = g_hist[(q << 8) + b];
            if (c + h >= kr) {
                g_prefix[q] |= ((unsigned)b) << shift;
                g_krem[q] = (int)(kr - c);
                found = 1;
                break;
            }
            c += h;
        }
        if (!found) g_keepall[q] = 1;
    }
    __syncthreads();
    for (int t = threadIdx.x; t < NQ * 256; t += blockDim.x) g_hist[t] = 0u;
}
__global__ void k_eq_gather(const int* __restrict__ qidx, int E) {
    int e = blockIdx.x * blockDim.x + threadIdx.x;
    if (e >= E) return;
    int q = qidx[e];
    if (g_keepall[q]) return;
    if (g_ukey[e] == g_prefix[q]) {
        int p = atomicAdd(&g_eqcnt[q], 1);
        if (p < EQCAP) g_eqlist[q * EQCAP + p] = e;
    }
}
__global__ void k_eq_resolve(int NQ) {
    int q = blockIdx.x;
    if (q >= NQ || g_keepall[q]) return;
    int n = min(g_eqcnt[q], EQCAP);
    int keq = g_krem[q];
    for (int t = threadIdx.x; t < n; t += blockDim.x) {
        int me = g_eqlist[q * EQCAP + t];
        if (n <= keq) { g_eqkeep[me] = 1; continue; }
        int cnt = 0;
        for (int jj = 0; jj < n; jj++) cnt += (g_eqlist[q * EQCAP + jj] < me);
        if (cnt < keq) g_eqkeep[me] = 1;
    }
}

// ---------------- pruned aggregation ----------------
__global__ void k_aggregate(const float* __restrict__ node_rep, const int* __restrict__ qidx,
                            const int* __restrict__ idx_i, const int* __restrict__ idx_j,
                            float* __restrict__ out_score, int E) {
    int w = (blockIdx.x * blockDim.x + threadIdx.x) >> 5;
    int lane = threadIdx.x & 31;
    if (w >= E) return;
    int q = qidx[w];
    bool keep = g_keepall[q] || (g_ukey[w] > g_prefix[q]) || g_eqkeep[w];
    if (!keep) return;
    int i = idx_i[w], j = idx_j[w];
    if (lane == 0) atomicAdd(out_score + j, g_scoreE[w]);
    float a = g_attn[w];
    float4 h = *(const float4*)(node_rep + (size_t)i * D + lane * 4);
#if __CUDA_ARCH__ >= 900
    atomicAdd((float4*)(g_newrep + (size_t)j * D + lane * 4),
              make_float4(a * h.x, a * h.y, a * h.z, a * h.w));
#else
    float* dst = g_newrep + (size_t)j * D + lane * 4;
    atomicAdd(dst + 0, a * h.x);
    atomicAdd(dst + 1, a * h.y);
    atomicAdd(dst + 2, a * h.z);
    atomicAdd(dst + 3, a * h.w);
#endif
}

// ---------------- launch ----------------
extern "C" void kernel_launch(void* const* d_in, const int* in_sizes, int n_in,
                              void* d_out, int out_size) {
    const float* visited  = (const float*)d_in[0];
    const float* node_rep = (const float*)d_in[1];
    const float* qsrc     = (const float*)d_in[2];
    const float* qrel     = (const float*)d_in[3];
    const float* rel      = (const float*)d_in[4];
    const float* W_left   = (const float*)d_in[5];
    const float* b_left   = (const float*)d_in[6];
    const float* W_right  = (const float*)d_in[7];
    const float* b_right  = (const float*)d_in[8];
    const float* W_center = (const float*)d_in[9];
    const float* b_center = (const float*)d_in[10];
    const float* W_step   = (const float*)d_in[11];
    const float* b_step   = (const float*)d_in[12];
    const int* query_idx  = (const int*)d_in[13];
    const int* idx_i      = (const int*)d_in[14];
    const int* idx_j      = (const int*)d_in[15];
    const int* max_edges  = (n_in >= 17) ? (const int*)d_in[16] : nullptr;

    int NN = in_sizes[0];
    int E  = in_sizes[13];
    int NQ = in_sizes[2] / D;

    float* out_score = (float*)d_out;
    float* out_rep   = (float*)d_out + NN;

    void* p;
    cudaGetSymbolAddress(&p, g_Pnode);  float* Pnode  = (float*)p;
    cudaGetSymbolAddress(&p, g_Prel);   float* Prel   = (float*)p;
    cudaGetSymbolAddress(&p, g_R);      float* Rbuf   = (float*)p;
    cudaGetSymbolAddress(&p, g_Qc);     float* Qc     = (float*)p;
    cudaGetSymbolAddress(&p, g_newrep); float* newrep = (float*)p;
    cudaGetSymbolAddress(&p, g_WnodeH); __half* WnodeH = (__half*)p;
    cudaGetSymbolAddress(&p, g_WnodeL); __half* WnodeL = (__half*)p;
    cudaGetSymbolAddress(&p, g_WrelH);  __half* WrelH  = (__half*)p;
    cudaGetSymbolAddress(&p, g_WrelL);  __half* WrelL  = (__half*)p;
    cudaGetSymbolAddress(&p, g_WqH);    __half* WqH    = (__half*)p;
    cudaGetSymbolAddress(&p, g_WqL);    __half* WqL    = (__half*)p;
    cudaGetSymbolAddress(&p, g_WcH);    __half* WcH    = (__half*)p;
    cudaGetSymbolAddress(&p, g_WcL);    __half* WcL    = (__half*)p;
    cudaGetSymbolAddress(&p, g_WsH);    __half* WsH    = (__half*)p;
    cudaGetSymbolAddress(&p, g_WsL);    __half* WsL    = (__half*)p;
    cudaGetSymbolAddress(&p, g_QinH);   __half* QinH   = (__half*)p;
    cudaGetSymbolAddress(&p, g_QinL);   __half* QinL   = (__half*)p;
    cudaGetSymbolAddress(&p, g_NodeH);  __half* NodeH  = (__half*)p;
    cudaGetSymbolAddress(&p, g_NodeL);  __half* NodeL  = (__half*)p;
    cudaGetSymbolAddress(&p, g_RelH);   __half* RelH   = (__half*)p;
    cudaGetSymbolAddress(&p, g_RelL);   __half* RelL   = (__half*)p;
    cudaGetSymbolAddress(&p, g_R1H);    __half* R1H    = (__half*)p;
    cudaGetSymbolAddress(&p, g_R1L);    __half* R1L    = (__half*)p;
    cudaGetSymbolAddress(&p, g_NrH);    __half* NrH    = (__half*)p;
    cudaGetSymbolAddress(&p, g_NrL);    __half* NrL    = (__half*)p;

    static int smem_set = 0;
    if (!smem_set) {
        cudaFuncSetAttribute(gemm_f16<false>, cudaFuncAttributeMaxDynamicSharedMemorySize, GEMM_SMEM_BYTES);
        cudaFuncSetAttribute(gemm_f16<true>,  cudaFuncAttributeMaxDynamicSharedMemorySize, GEMM_SMEM_BYTES);
        smem_set = 1;
    }

    const int T = 256;
    // --- init state ---
    kzero_f<<<(NN + T - 1) / T, T>>>(out_score, NN);
    {
        int mx = NN > E ? NN : E;
        if (NQ * 256 > mx) mx = NQ * 256;
        k_zero_state<<<(mx + T - 1) / T, T>>>(NN, E, NQ);
    }
    // --- operand prep: repack + split to fp16 hi/lo ---
    k_prep<<<(512 * 512 + T - 1) / T, T>>>(W_left, W_right);
    k_split<<<(256 * 256 / 4 + T - 1) / T, T>>>(W_center, WcH, WcL, 256 * 256 / 4);
    k_split<<<(128 * 128 / 4 + T - 1) / T, T>>>(W_step, WsH, WsL, 128 * 128 / 4);
    k_qin<<<(NQ * 256 + T - 1) / T, T>>>(qsrc, qrel, NQ);
    k_split<<<((NN * 128 / 4) + T - 1) / T, T>>>(node_rep, NodeH, NodeL, NN * 128 / 4);
    k_split<<<((E * 128 / 4) + T - 1) / T, T>>>(rel, RelH, RelL, E * 128 / 4);
    // --- GEMMs on tensor pipe (fp16 3-pass split) ---
    gemm_f16<false><<<dim3(4, (NQ + 127) / 128), T, GEMM_SMEM_BYTES>>>(QinH, QinL, WqH, WqL, Qc, nullptr, NQ, 512, 256);
    gemm_f16<false><<<dim3(4, (NN + 127) / 128), T, GEMM_SMEM_BYTES>>>(NodeH, NodeL, WnodeH, WnodeL, Pnode, nullptr, NN, 512, 128);
    gemm_f16<false><<<dim3(4, (E + 127) / 128), T, GEMM_SMEM_BYTES>>>(RelH, RelL, WrelH, WrelL, Prel, nullptr, E, 512, 128);
    // --- per-edge assemble (writes L fp32 + R1 split fp16) ---
    k_assemble<<<((size_t)E * 64 + T - 1) / T, T>>>(idx_i, idx_j, query_idx, b_left, b_right, E);
    // --- center GEMM ---
    gemm_f16<false><<<dim3(2, (E + 127) / 128), T, GEMM_SMEM_BYTES>>>(R1H, R1L, WcH, WcL, Rbuf, nullptr, E, 256, 256);
    // --- logits + segment softmax ---
    k_logits<<<((size_t)E * 32 + T - 1) / T, T>>>(b_center, idx_i, E);
    k_ex<<<(E + T - 1) / T, T>>>(idx_i, E);
    k_score<<<(E + T - 1) / T, T>>>(idx_i, visited, E);
    // --- per-query exact top-k ---
    k_init_select<<<(NQ + T - 1) / T, T>>>(max_edges, NQ);
    int shifts[4] = {24, 16, 8, 0};
    for (int pp = 0; pp < 4; pp++) {
        k_hist<<<(E + T - 1) / T, T>>>(query_idx, E, shifts[pp]);
        k_scan<<<1, 256>>>(shifts[pp], NQ);
    }
    k_eq_gather<<<(E + T - 1) / T, T>>>(query_idx, E);
    k_eq_resolve<<<NQ, 128>>>(NQ);
    // --- aggregation ---
    cudaMemcpyAsync(newrep, node_rep, (size_t)NN * D * sizeof(float),
                    cudaMemcpyDeviceToDevice, 0);
    k_aggregate<<<((size_t)E * 32 + T - 1) / T, T>>>(node_rep, query_idx, idx_i, idx_j, out_score, E);
    // --- step GEMM with bias + leaky ---
    k_split<<<((NN * 128 / 4) + T - 1) / T, T>>>(newrep, NrH, NrL, NN * 128 / 4);
    gemm_f16<true><<<dim3(1, (NN + 127) / 128), T, GEMM_SMEM_BYTES>>>(NrH, NrL, WsH, WsL, out_rep, b_step, NN, 128, 128);
    (void)out_size;
}

// round 9
// speedup vs baseline: 2.0033x; 1.0729x over previous
#include <cuda_runtime.h>
#include <cuda_fp16.h>
#include <cstdint>
#include <math.h>

#define D 128
#define NMAX 100352
#define EMAX 131072
#define NQMAX 128
#define EQCAP 1024

// ---------------- static scratch (allocation-free rule) ----------------
__device__ float    g_Qc   [NQMAX * 512];       // query combined (+bias folded)
__device__ float    g_bcat [512];               // [b_left ; b_right]
__device__ float    g_Pnode[NMAX * 512];
__device__ float    g_L  [EMAX * 256];
__device__ float    g_logits[EMAX];
__device__ float    g_ex[EMAX];
__device__ float    g_attn[EMAX];
__device__ float    g_scoreE[EMAX];
__device__ unsigned g_ukey[EMAX];
__device__ unsigned g_segmax[NMAX];
__device__ float    g_denom[NMAX];
__device__ float    g_newrep[NMAX * D];
__device__ unsigned g_hist[NQMAX * 256];
__device__ unsigned g_prefix[NQMAX];
__device__ int      g_krem[NQMAX];
__device__ int      g_keepall[NQMAX];
__device__ int      g_eqcnt[NQMAX];
__device__ int      g_eqlist[NQMAX * EQCAP];
__device__ int      g_eqkeep[EMAX];

// split fp16 operand buffers (hi/lo)
__device__ __align__(128) __half g_WnodeH[512 * 128], g_WnodeL[512 * 128];
__device__ __align__(128) __half g_WrelH [512 * 128], g_WrelL [512 * 128];
__device__ __align__(128) __half g_WqH   [512 * 256], g_WqL   [512 * 256];
__device__ __align__(128) __half g_WcH   [256 * 256], g_WcL   [256 * 256];
__device__ __align__(128) __half g_WsH   [128 * 128], g_WsL   [128 * 128];
__device__ __align__(128) __half g_QinH  [NQMAX * 256], g_QinL[NQMAX * 256];
__device__ __align__(128) __half g_NodeH [NMAX * 128], g_NodeL[NMAX * 128];
__device__ __align__(128) __half g_RelH  [EMAX * 128], g_RelL [EMAX * 128];
__device__ __align__(128) __half g_R1H   [EMAX * 256], g_R1L  [EMAX * 256];
__device__ __align__(128) __half g_NrH   [NMAX * 128], g_NrL  [NMAX * 128];

__device__ __forceinline__ float leaky(float x) { return x > 0.f ? x : 0.01f * x; }
__device__ __forceinline__ unsigned f2mono(float f) {
    unsigned b = __float_as_uint(f);
    return (b & 0x80000000u) ? ~b : (b | 0x80000000u);
}
__device__ __forceinline__ float mono2f(unsigned u) {
    return (u & 0x80000000u) ? __uint_as_float(u & 0x7fffffffu) : __uint_as_float(~u);
}
__device__ __forceinline__ uint32_t smem_u32(const void* p) {
    uint32_t a;
    asm("{ .reg .u64 t; cvta.to.shared.u64 t, %1; cvt.u32.u64 %0, t; }" : "=r"(a) : "l"(p));
    return a;
}
__device__ __forceinline__ void split_h(float v, __half& h, __half& l) {
    h = __float2half_rn(v);
    l = __float2half_rn(v - __half2float(h));
}
__device__ __forceinline__ void ldsm4(uint32_t* r, uint32_t addr) {
    asm volatile("ldmatrix.sync.aligned.m8n8.x4.shared.b16 {%0,%1,%2,%3}, [%4];"
                 : "=r"(r[0]), "=r"(r[1]), "=r"(r[2]), "=r"(r[3]) : "r"(addr));
}
__device__ __forceinline__ void mma_f16(float* d, const uint32_t* a, const uint32_t* b) {
    asm volatile(
        "mma.sync.aligned.m16n8k16.row.col.f32.f16.f16.f32 "
        "{%0,%1,%2,%3}, {%4,%5,%6,%7}, {%8,%9}, {%0,%1,%2,%3};"
        : "+f"(d[0]), "+f"(d[1]), "+f"(d[2]), "+f"(d[3])
        : "r"(a[0]), "r"(a[1]), "r"(a[2]), "r"(a[3]), "r"(b[0]), "r"(b[1]));
}

// ================= fp16 3-pass split GEMM: C[M,N] = A[M,K] @ B[N,K]^T =================
// MODE 0: plain store   1: bias+leaky store   2: bias store
// MODE 3: assemble-fused epilogue (Prel GEMM): gathers Pnode/Qc, leaky, writes L + split R1
// MODE 4: logits-fused epilogue (center GEMM): partial dot with L, atomicAdd into g_logits
#define ROWH 40
#define TILE_H (128 * ROWH)
#define STAGE_H (4 * TILE_H)
#define GEMM_SMEM_BYTES (2 * STAGE_H * 2)  // 81920 bytes
template <int MODE>
__global__ __launch_bounds__(256) void gemm_f16(const __half* __restrict__ Ah,
                                                const __half* __restrict__ Al,
                                                const __half* __restrict__ Bh,
                                                const __half* __restrict__ Bl,
                                                float* __restrict__ C,
                                                const float* __restrict__ bias,
                                                int M, int N, int K,
                                                const int* __restrict__ idx_i,
                                                const int* __restrict__ idx_j,
                                                const int* __restrict__ qidx,
                                                const float* __restrict__ Pn,
                                                const float* __restrict__ Qc2,
                                                float* __restrict__ outL,
                                                __half* __restrict__ outRH,
                                                __half* __restrict__ outRL,
                                                const float* __restrict__ Lbuf) {
    extern __shared__ __align__(128) __half sm[];
    const int tid = threadIdx.x, lane = tid & 31, wid = tid >> 5;
    const int wm = wid & 1, wn = wid >> 1;
    const int bm = blockIdx.y * 128, bn = blockIdx.x * 128;
    const int rl = lane & 7, q = lane >> 3;

    float acc[4][4][4];
#pragma unroll
    for (int mt = 0; mt < 4; mt++)
#pragma unroll
        for (int nt = 0; nt < 4; nt++)
#pragma unroll
            for (int r = 0; r < 4; r++) acc[mt][nt][r] = 0.f;

#define LOAD_STAGE(st, kc)                                                               \
    do {                                                                                 \
        _Pragma("unroll")                                                                \
        for (int i = 0; i < 8; i++) {                                                    \
            int ch = tid + i * 256;                                                      \
            int tile = ch >> 9, r = (ch >> 2) & 127, seg = ch & 3;                       \
            const __half* src;                                                           \
            int sz = 16;                                                                 \
            if (tile < 2) {                                                              \
                int row = bm + r;                                                        \
                int rc = row < M ? row : 0;                                              \
                sz = row < M ? 16 : 0;                                                   \
                src = (tile == 0 ? Ah : Al) + (size_t)rc * K + (kc) + seg * 8;           \
            } else {                                                                     \
                int row = bn + r;                                                        \
                src = (tile == 2 ? Bh : Bl) + (size_t)row * K + (kc) + seg * 8;          \
            }                                                                            \
            uint32_t dst = smem_u32(sm + (st)*STAGE_H + tile * TILE_H + r * ROWH + seg * 8); \
            asm volatile("cp.async.cg.shared.global [%0], [%1], 16, %2;"                 \
                         :: "r"(dst), "l"(src), "r"(sz));                                \
        }                                                                                \
        asm volatile("cp.async.commit_group;" ::: "memory");                             \
    } while (0)

    const int nch = K >> 5;
    LOAD_STAGE(0, 0);

    for (int c = 0; c < nch; c++) {
        if (c + 1 < nch) {
            LOAD_STAGE((c + 1) & 1, (c + 1) << 5);
            asm volatile("cp.async.wait_group 1;" ::: "memory");
        } else {
            asm volatile("cp.async.wait_group 0;" ::: "memory");
        }
        __syncthreads();

        const __half* base = sm + (c & 1) * STAGE_H;
        uint32_t aAh = smem_u32(base);
        uint32_t aAl = smem_u32(base + TILE_H);
        uint32_t aBh = smem_u32(base + 2 * TILE_H);
        uint32_t aBl = smem_u32(base + 3 * TILE_H);

#pragma unroll
        for (int ks = 0; ks < 2; ks++) {
            uint32_t ah[4][4], al[4][4], bh[4][2], bl[4][2];
#pragma unroll
            for (int mt = 0; mt < 4; mt++) {
                uint32_t off = ((wm * 64 + mt * 16 + (q & 1) * 8 + rl) * ROWH +
                                ks * 16 + (q >> 1) * 8) * 2;
                ldsm4(ah[mt], aAh + off);
                ldsm4(al[mt], aAl + off);
            }
#pragma unroll
            for (int p = 0; p < 2; p++) {
                uint32_t off = ((wn * 32 + p * 16 + (q >> 1) * 8 + rl) * ROWH +
                                ks * 16 + (q & 1) * 8) * 2;
                uint32_t t[4];
                ldsm4(t, aBh + off);
                bh[2 * p][0] = t[0]; bh[2 * p][1] = t[1];
                bh[2 * p + 1][0] = t[2]; bh[2 * p + 1][1] = t[3];
                ldsm4(t, aBl + off);
                bl[2 * p][0] = t[0]; bl[2 * p][1] = t[1];
                bl[2 * p + 1][0] = t[2]; bl[2 * p + 1][1] = t[3];
            }
#pragma unroll
            for (int mt = 0; mt < 4; mt++)
#pragma unroll
                for (int nt = 0; nt < 4; nt++) {
                    mma_f16(acc[mt][nt], ah[mt], bh[nt]);
                    mma_f16(acc[mt][nt], ah[mt], bl[nt]);
                    mma_f16(acc[mt][nt], al[mt], bh[nt]);
                }
        }
        __syncthreads();
    }

    // ---- epilogues ----
    const int g = lane >> 2, t4 = lane & 3;

    if constexpr (MODE == 3) {
        // stage this tile's edge indices in smem (reuse GEMM smem; mainloop fully synced)
        int* si = (int*)sm;
        if (tid < 128) {
            int e = bm + tid;
            si[tid] = idx_i[e];
            si[128 + tid] = idx_j[e];
            si[256 + tid] = qidx[e];
        }
        __syncthreads();
#pragma unroll
        for (int mt = 0; mt < 4; mt++) {
            int rl0 = wm * 64 + mt * 16 + g;
            int i0 = si[rl0], j0 = si[128 + rl0], q0 = si[256 + rl0];
            int i1 = si[rl0 + 8], j1 = si[128 + rl0 + 8], q1 = si[256 + rl0 + 8];
            size_t e0 = (size_t)bm + rl0, e1 = e0 + 8;
#pragma unroll
            for (int nt = 0; nt < 4; nt++) {
                int col = bn + wn * 32 + nt * 8 + t4 * 2;
                bool left = col < 256;
                int b0 = left ? i0 : j0, b1 = left ? i1 : j1;
                float2 pn0 = *(const float2*)(Pn + (size_t)b0 * 512 + col);
                float2 qc0 = *(const float2*)(Qc2 + (size_t)q0 * 512 + col);
                float2 pn1 = *(const float2*)(Pn + (size_t)b1 * 512 + col);
                float2 qc1 = *(const float2*)(Qc2 + (size_t)q1 * 512 + col);
                float v0 = leaky(acc[mt][nt][0] + pn0.x + qc0.x);
                float v1 = leaky(acc[mt][nt][1] + pn0.y + qc0.y);
                float v2 = leaky(acc[mt][nt][2] + pn1.x + qc1.x);
                float v3 = leaky(acc[mt][nt][3] + pn1.y + qc1.y);
                if (left) {
                    *(float2*)(outL + e0 * 256 + col) = make_float2(v0, v1);
                    *(float2*)(outL + e1 * 256 + col) = make_float2(v2, v3);
                } else {
                    __half h0, l0, h1, l1, h2, l2, h3, l3;
                    split_h(v0, h0, l0); split_h(v1, h1, l1);
                    split_h(v2, h2, l2); split_h(v3, h3, l3);
                    size_t o0 = e0 * 256 + col - 256, o1 = e1 * 256 + col - 256;
                    *(__half2*)(outRH + o0) = __halves2half2(h0, h1);
                    *(__half2*)(outRL + o0) = __halves2half2(l0, l1);
                    *(__half2*)(outRH + o1) = __halves2half2(h2, h3);
                    *(__half2*)(outRL + o1) = __halves2half2(l2, l3);
                }
            }
        }
    } else if constexpr (MODE == 4) {
#pragma unroll
        for (int mt = 0; mt < 4; mt++) {
            int r0 = bm + wm * 64 + mt * 16 + g;
            float p0 = 0.f, p1 = 0.f;
#pragma unroll
            for (int nt = 0; nt < 4; nt++) {
                int col = bn + wn * 32 + nt * 8 + t4 * 2;
                float b0 = bias[col], b1 = bias[col + 1];
                float2 l0 = *(const float2*)(Lbuf + (size_t)r0 * 256 + col);
                float2 l1 = *(const float2*)(Lbuf + (size_t)(r0 + 8) * 256 + col);
                p0 = fmaf(l0.x, acc[mt][nt][0] + b0, p0);
                p0 = fmaf(l0.y, acc[mt][nt][1] + b1, p0);
                p1 = fmaf(l1.x, acc[mt][nt][2] + b0, p1);
                p1 = fmaf(l1.y, acc[mt][nt][3] + b1, p1);
            }
            p0 += __shfl_xor_sync(0xffffffffu, p0, 1);
            p0 += __shfl_xor_sync(0xffffffffu, p0, 2);
            p1 += __shfl_xor_sync(0xffffffffu, p1, 1);
            p1 += __shfl_xor_sync(0xffffffffu, p1, 2);
            if (t4 == 0) {
                atomicAdd(&g_logits[r0], p0);
                atomicAdd(&g_logits[r0 + 8], p1);
            }
        }
    } else {
#pragma unroll
        for (int mt = 0; mt < 4; mt++) {
            int row0 = bm + wm * 64 + mt * 16 + g;
#pragma unroll
            for (int nt = 0; nt < 4; nt++) {
                int col = bn + wn * 32 + nt * 8 + t4 * 2;
                float d0 = acc[mt][nt][0], d1 = acc[mt][nt][1];
                float d2 = acc[mt][nt][2], d3 = acc[mt][nt][3];
                if (MODE == 1 || MODE == 2) {
                    float b0 = bias[col], b1 = bias[col + 1];
                    d0 += b0; d1 += b1; d2 += b0; d3 += b1;
                    if (MODE == 1) {
                        d0 = leaky(d0); d1 = leaky(d1);
                        d2 = leaky(d2); d3 = leaky(d3);
                    }
                }
                if (row0 < M) *(float2*)(C + (size_t)row0 * N + col) = make_float2(d0, d1);
                if (row0 + 8 < M) *(float2*)(C + (size_t)(row0 + 8) * N + col) = make_float2(d2, d3);
            }
        }
    }
}

// ---------------- misc small kernels ----------------
__global__ void kzero_f(float* p, int n) {
    int i = blockIdx.x * blockDim.x + threadIdx.x;
    if (i < n) p[i] = 0.f;
}
__global__ void k_zero_state(int NN, int E, int NQ) {
    int t = blockIdx.x * blockDim.x + threadIdx.x;
    if (t < NN) { g_segmax[t] = 0u; g_denom[t] = 0.f; }
    if (t < E)  { g_eqkeep[t] = 0; g_logits[t] = 0.f; }
    if (t < NQ * 256) g_hist[t] = 0u;
}

// generic fp32 -> split fp16 (hi/lo), n4 = n/4
__global__ void k_split(const float* __restrict__ src, __half* __restrict__ hi,
                        __half* __restrict__ lo, int n4) {
    int i = blockIdx.x * blockDim.x + threadIdx.x;
    if (i >= n4) return;
    float4 v = ((const float4*)src)[i];
    __half h0, h1, h2, h3, l0, l1, l2, l3;
    split_h(v.x, h0, l0); split_h(v.y, h1, l1);
    split_h(v.z, h2, l2); split_h(v.w, h3, l3);
    ((__half2*)hi)[i * 2 + 0] = __halves2half2(h0, h1);
    ((__half2*)hi)[i * 2 + 1] = __halves2half2(h2, h3);
    ((__half2*)lo)[i * 2 + 0] = __halves2half2(l0, l1);
    ((__half2*)lo)[i * 2 + 1] = __halves2half2(l2, l3);
}

// weight repack + split
__global__ void k_prep(const float* __restrict__ Wl, const float* __restrict__ Wr) {
    int t = blockIdx.x * blockDim.x + threadIdx.x;
    if (t >= 512 * 512) return;
    int j = t >> 9, k = t & 511;
    float v = (j < 256) ? Wl[(size_t)j * 512 + k] : Wr[(size_t)(j - 256) * 512 + k];
    __half h, l;
    split_h(v, h, l);
    if (k < 128)      { g_WnodeH[j * 128 + k] = h;         g_WnodeL[j * 128 + k] = l; }
    else if (k < 256) { g_WrelH[j * 128 + k - 128] = h;    g_WrelL[j * 128 + k - 128] = l; }
    else              { g_WqH[j * 256 + k - 256] = h;      g_WqL[j * 256 + k - 256] = l; }
}
__global__ void k_qin(const float* __restrict__ qs, const float* __restrict__ qr,
                      const float* __restrict__ bl, const float* __restrict__ br, int NQ) {
    int t = blockIdx.x * blockDim.x + threadIdx.x;
    if (t < 512) g_bcat[t] = (t < 256) ? bl[t] : br[t - 256];
    if (t >= NQ * 256) return;
    int q = t >> 8, k = t & 255;
    float v = (k < 128) ? qs[q * 128 + k] : qr[q * 128 + (k - 128)];
    __half h, l;
    split_h(v, h, l);
    g_QinH[t] = h;
    g_QinL[t] = l;
}

// segment max over logits
__global__ void k_segmax(const int* __restrict__ idx_i, int E) {
    int e = blockIdx.x * blockDim.x + threadIdx.x;
    if (e >= E) return;
    atomicMax(&g_segmax[idx_i[e]], f2mono(g_logits[e]));
}
__global__ void k_ex(const int* __restrict__ idx_i, int E) {
    int e = blockIdx.x * blockDim.x + threadIdx.x;
    if (e >= E) return;
    int i = idx_i[e];
    float m = mono2f(g_segmax[i]);
    float ex = expf(g_logits[e] - m);
    g_ex[e] = ex;
    atomicAdd(&g_denom[i], ex);
}
__global__ void k_score(const int* __restrict__ idx_i, const float* __restrict__ visited, int E) {
    int e = blockIdx.x * blockDim.x + threadIdx.x;
    if (e >= E) return;
    int i = idx_i[e];
    float a = g_ex[e] / g_denom[i];
    g_attn[e] = a;
    float sc = a * visited[i];
    g_scoreE[e] = sc;
    g_ukey[e] = __float_as_uint(sc);
}

// ---------------- top-k radix select ----------------
__global__ void k_init_select(const int* __restrict__ max_edges, int NQ) {
    int q = blockIdx.x * blockDim.x + threadIdx.x;
    if (q < NQ) {
        g_krem[q] = max_edges ? *max_edges : 1024;
        g_prefix[q] = 0u;
        g_keepall[q] = 0;
        g_eqcnt[q] = 0;
    }
}
__global__ void k_hist(const int* __restrict__ qidx, int E, int shift) {
    int e = blockIdx.x * blockDim.x + threadIdx.x;
    if (e >= E) return;
    int q = qidx[e];
    if (g_keepall[q]) return;
    unsigned u = g_ukey[e];
    if (shift < 24 && ((u >> (shift + 8)) != (g_prefix[q] >> (shift + 8)))) return;
    atomicAdd(&g_hist[(q << 8) + ((u >> shift) & 255u)], 1u);
}
__global__ void k_scan(int shift, int NQ) {
    int q = threadIdx.x;
    if (q < NQ && !g_keepall[q]) {
        unsigned kr = (unsigned)g_krem[q];
        unsigned c = 0;
        int found = 0;
        for (int b = 255; b >= 0; b--) {
            unsigned h = g_hist[(q << 8) + b];
            if (c + h >= kr) {
                g_prefix[q] |= ((unsigned)b) << shift;
                g_krem[q] = (int)(kr - c);
                found = 1;
                break;
            }
            c += h;
        }
        if (!found) g_keepall[q] = 1;
    }
    __syncthreads();
    for (int t = threadIdx.x; t < NQ * 256; t += blockDim.x) g_hist[t] = 0u;
}
__global__ void k_eq_gather(const int* __restrict__ qidx, int E) {
    int e = blockIdx.x * blockDim.x + threadIdx.x;
    if (e >= E) return;
    int q = qidx[e];
    if (g_keepall[q]) return;
    if (g_ukey[e] == g_prefix[q]) {
        int p = atomicAdd(&g_eqcnt[q], 1);
        if (p < EQCAP) g_eqlist[q * EQCAP + p] = e;
    }
}
__global__ void k_eq_resolve(int NQ) {
    int q = blockIdx.x;
    if (q >= NQ || g_keepall[q]) return;
    int n = min(g_eqcnt[q], EQCAP);
    int keq = g_krem[q];
    for (int t = threadIdx.x; t < n; t += blockDim.x) {
        int me = g_eqlist[q * EQCAP + t];
        if (n <= keq) { g_eqkeep[me] = 1; continue; }
        int cnt = 0;
        for (int jj = 0; jj < n; jj++) cnt += (g_eqlist[q * EQCAP + jj] < me);
        if (cnt < keq) g_eqkeep[me] = 1;
    }
}

// ---------------- pruned aggregation ----------------
__global__ void k_aggregate(const float* __restrict__ node_rep, const int* __restrict__ qidx,
                            const int* __restrict__ idx_i, const int* __restrict__ idx_j,
                            float* __restrict__ out_score, int E) {
    int w = (blockIdx.x * blockDim.x + threadIdx.x) >> 5;
    int lane = threadIdx.x & 31;
    if (w >= E) return;
    int q = qidx[w];
    bool keep = g_keepall[q] || (g_ukey[w] > g_prefix[q]) || g_eqkeep[w];
    if (!keep) return;
    int i = idx_i[w], j = idx_j[w];
    if (lane == 0) atomicAdd(out_score + j, g_scoreE[w]);
    float a = g_attn[w];
    float4 h = *(const float4*)(node_rep + (size_t)i * D + lane * 4);
#if __CUDA_ARCH__ >= 900
    atomicAdd((float4*)(g_newrep + (size_t)j * D + lane * 4),
              make_float4(a * h.x, a * h.y, a * h.z, a * h.w));
#else
    float* dst = g_newrep + (size_t)j * D + lane * 4;
    atomicAdd(dst + 0, a * h.x);
    atomicAdd(dst + 1, a * h.y);
    atomicAdd(dst + 2, a * h.z);
    atomicAdd(dst + 3, a * h.w);
#endif
}

// ---------------- launch ----------------
extern "C" void kernel_launch(void* const* d_in, const int* in_sizes, int n_in,
                              void* d_out, int out_size) {
    const float* visited  = (const float*)d_in[0];
    const float* node_rep = (const float*)d_in[1];
    const float* qsrc     = (const float*)d_in[2];
    const float* qrel     = (const float*)d_in[3];
    const float* rel      = (const float*)d_in[4];
    const float* W_left   = (const float*)d_in[5];
    const float* b_left   = (const float*)d_in[6];
    const float* W_right  = (const float*)d_in[7];
    const float* b_right  = (const float*)d_in[8];
    const float* W_center = (const float*)d_in[9];
    const float* b_center = (const float*)d_in[10];
    const float* W_step   = (const float*)d_in[11];
    const float* b_step   = (const float*)d_in[12];
    const int* query_idx  = (const int*)d_in[13];
    const int* idx_i      = (const int*)d_in[14];
    const int* idx_j      = (const int*)d_in[15];
    const int* max_edges  = (n_in >= 17) ? (const int*)d_in[16] : nullptr;

    int NN = in_sizes[0];
    int E  = in_sizes[13];
    int NQ = in_sizes[2] / D;

    float* out_score = (float*)d_out;
    float* out_rep   = (float*)d_out + NN;

    void* p;
    cudaGetSymbolAddress(&p, g_Pnode);  float* Pnode  = (float*)p;
    cudaGetSymbolAddress(&p, g_Qc);     float* Qc     = (float*)p;
    cudaGetSymbolAddress(&p, g_bcat);   float* bcat   = (float*)p;
    cudaGetSymbolAddress(&p, g_L);      float* Lbuf   = (float*)p;
    cudaGetSymbolAddress(&p, g_newrep); float* newrep = (float*)p;
    cudaGetSymbolAddress(&p, g_WnodeH); __half* WnodeH = (__half*)p;
    cudaGetSymbolAddress(&p, g_WnodeL); __half* WnodeL = (__half*)p;
    cudaGetSymbolAddress(&p, g_WrelH);  __half* WrelH  = (__half*)p;
    cudaGetSymbolAddress(&p, g_WrelL);  __half* WrelL  = (__half*)p;
    cudaGetSymbolAddress(&p, g_WqH);    __half* WqH    = (__half*)p;
    cudaGetSymbolAddress(&p, g_WqL);    __half* WqL    = (__half*)p;
    cudaGetSymbolAddress(&p, g_WcH);    __half* WcH    = (__half*)p;
    cudaGetSymbolAddress(&p, g_WcL);    __half* WcL    = (__half*)p;
    cudaGetSymbolAddress(&p, g_WsH);    __half* WsH    = (__half*)p;
    cudaGetSymbolAddress(&p, g_WsL);    __half* WsL    = (__half*)p;
    cudaGetSymbolAddress(&p, g_QinH);   __half* QinH   = (__half*)p;
    cudaGetSymbolAddress(&p, g_QinL);   __half* QinL   = (__half*)p;
    cudaGetSymbolAddress(&p, g_NodeH);  __half* NodeH  = (__half*)p;
    cudaGetSymbolAddress(&p, g_NodeL);  __half* NodeL  = (__half*)p;
    cudaGetSymbolAddress(&p, g_RelH);   __half* RelH   = (__half*)p;
    cudaGetSymbolAddress(&p, g_RelL);   __half* RelL   = (__half*)p;
    cudaGetSymbolAddress(&p, g_R1H);    __half* R1H    = (__half*)p;
    cudaGetSymbolAddress(&p, g_R1L);    __half* R1L    = (__half*)p;
    cudaGetSymbolAddress(&p, g_NrH);    __half* NrH    = (__half*)p;
    cudaGetSymbolAddress(&p, g_NrL);    __half* NrL    = (__half*)p;

    static int smem_set = 0;
    if (!smem_set) {
        cudaFuncSetAttribute(gemm_f16<0>, cudaFuncAttributeMaxDynamicSharedMemorySize, GEMM_SMEM_BYTES);
        cudaFuncSetAttribute(gemm_f16<1>, cudaFuncAttributeMaxDynamicSharedMemorySize, GEMM_SMEM_BYTES);
        cudaFuncSetAttribute(gemm_f16<2>, cudaFuncAttributeMaxDynamicSharedMemorySize, GEMM_SMEM_BYTES);
        cudaFuncSetAttribute(gemm_f16<3>, cudaFuncAttributeMaxDynamicSharedMemorySize, GEMM_SMEM_BYTES);
        cudaFuncSetAttribute(gemm_f16<4>, cudaFuncAttributeMaxDynamicSharedMemorySize, GEMM_SMEM_BYTES);
        smem_set = 1;
    }

    const int T = 256;
    // --- init state ---
    kzero_f<<<(NN + T - 1) / T, T>>>(out_score, NN);
    {
        int mx = NN > E ? NN : E;
        if (NQ * 256 > mx) mx = NQ * 256;
        k_zero_state<<<(mx + T - 1) / T, T>>>(NN, E, NQ);
    }
    // --- operand prep ---
    k_prep<<<(512 * 512 + T - 1) / T, T>>>(W_left, W_right);
    k_split<<<(256 * 256 / 4 + T - 1) / T, T>>>(W_center, WcH, WcL, 256 * 256 / 4);
    k_split<<<(128 * 128 / 4 + T - 1) / T, T>>>(W_step, WsH, WsL, 128 * 128 / 4);
    k_qin<<<(NQ * 256 + T - 1) / T, T>>>(qsrc, qrel, b_left, b_right, NQ);
    k_split<<<((NN * 128 / 4) + T - 1) / T, T>>>(node_rep, NodeH, NodeL, NN * 128 / 4);
    k_split<<<((E * 128 / 4) + T - 1) / T, T>>>(rel, RelH, RelL, E * 128 / 4);
    // --- Qc GEMM: bias-folded query term ---
    gemm_f16<2><<<dim3(4, (NQ + 127) / 128), T, GEMM_SMEM_BYTES>>>(
        QinH, QinL, WqH, WqL, Qc, bcat, NQ, 512, 256,
        nullptr, nullptr, nullptr, nullptr, nullptr, nullptr, nullptr, nullptr, nullptr);
    // --- Pnode GEMM ---
    gemm_f16<0><<<dim3(4, (NN + 127) / 128), T, GEMM_SMEM_BYTES>>>(
        NodeH, NodeL, WnodeH, WnodeL, Pnode, nullptr, NN, 512, 128,
        nullptr, nullptr, nullptr, nullptr, nullptr, nullptr, nullptr, nullptr, nullptr);
    // --- Prel GEMM, fused assemble epilogue: writes L (fp32) + R1 (split fp16) ---
    gemm_f16<3><<<dim3(4, (E + 127) / 128), T, GEMM_SMEM_BYTES>>>(
        RelH, RelL, WrelH, WrelL, nullptr, nullptr, E, 512, 128,
        idx_i, idx_j, query_idx, Pnode, Qc, Lbuf, R1H, R1L, nullptr);
    // --- center GEMM, fused logits epilogue: atomicAdd partial dots into g_logits ---
    gemm_f16<4><<<dim3(2, (E + 127) / 128), T, GEMM_SMEM_BYTES>>>(
        R1H, R1L, WcH, WcL, nullptr, b_center, E, 256, 256,
        nullptr, nullptr, nullptr, nullptr, nullptr, nullptr, nullptr, nullptr, Lbuf);
    // --- segment softmax ---
    k_segmax<<<(E + T - 1) / T, T>>>(idx_i, E);
    k_ex<<<(E + T - 1) / T, T>>>(idx_i, E);
    k_score<<<(E + T - 1) / T, T>>>(idx_i, visited, E);
    // --- per-query exact top-k ---
    k_init_select<<<(NQ + T - 1) / T, T>>>(max_edges, NQ);
    int shifts[4] = {24, 16, 8, 0};
    for (int pp = 0; pp < 4; pp++) {
        k_hist<<<(E + T - 1) / T, T>>>(query_idx, E, shifts[pp]);
        k_scan<<<1, 256>>>(shifts[pp], NQ);
    }
    k_eq_gather<<<(E + T - 1) / T, T>>>(query_idx, E);
    k_eq_resolve<<<NQ, 128>>>(NQ);
    // --- aggregation ---
    cudaMemcpyAsync(newrep, node_rep, (size_t)NN * D * sizeof(float),
                    cudaMemcpyDeviceToDevice, 0);
    k_aggregate<<<((size_t)E * 32 + T - 1) / T, T>>>(node_rep, query_idx, idx_i, idx_j, out_score, E);
    // --- step GEMM with bias + leaky ---
    k_split<<<((NN * 128 / 4) + T - 1) / T, T>>>(newrep, NrH, NrL, NN * 128 / 4);
    gemm_f16<1><<<dim3(1, (NN + 127) / 128), T, GEMM_SMEM_BYTES>>>(
        NrH, NrL, WsH, WsL, out_rep, b_step, NN, 128, 128,
        nullptr, nullptr, nullptr, nullptr, nullptr, nullptr, nullptr, nullptr, nullptr);
    (void)out_size;
}